// round 6
// baseline (speedup 1.0000x reference)
#include <cuda_runtime.h>
#include <cstdint>

#define D_MODEL 1024
#define LSEQ    2048
#define NB      2
#define NHEAD   16
#define HD      64
#define NTOK    (NB * LSEQ)   // 4096

__device__ float g_qkv[(size_t)NTOK * 3 * D_MODEL];   // [4096, 3072]
__device__ float g_attn[(size_t)NTOK * D_MODEL];      // [4096, 1024] = [B,L,H,hd]

// ---------------------------------------------------------------------------
// tf32 helpers
// ---------------------------------------------------------------------------
__device__ __forceinline__ uint32_t f2tf32(float f) {
    uint32_t r;
    asm("cvt.rna.tf32.f32 %0, %1;" : "=r"(r) : "f"(f));
    return r;
}

__device__ __forceinline__ void mma_tf32(float c[4], const uint32_t a[4], const uint32_t b[2]) {
    asm volatile(
        "mma.sync.aligned.m16n8k8.row.col.f32.tf32.tf32.f32 "
        "{%0,%1,%2,%3}, {%4,%5,%6,%7}, {%8,%9}, {%0,%1,%2,%3};"
        : "+f"(c[0]), "+f"(c[1]), "+f"(c[2]), "+f"(c[3])
        : "r"(a[0]), "r"(a[1]), "r"(a[2]), "r"(a[3]),
          "r"(b[0]), "r"(b[1]));
}

__device__ __forceinline__ void cp_async16(void* smem_dst, const void* gmem_src) {
    uint32_t dst;
    asm("{ .reg .u64 t; cvta.to.shared.u64 t, %1; cvt.u32.u64 %0, t; }"
        : "=r"(dst) : "l"(smem_dst));
    asm volatile("cp.async.cg.shared.global [%0], [%1], 16;" :: "r"(dst), "l"(gmem_src));
}
__device__ __forceinline__ void cp_async_commit() {
    asm volatile("cp.async.commit_group;");
}
template <int N>
__device__ __forceinline__ void cp_async_wait() {
    asm volatile("cp.async.wait_group %0;" :: "n"(N));
}

// ---------------------------------------------------------------------------
// tf32 tensor-core GEMM, 3-stage cp.async pipeline, ONE sync per k-iter.
// Invariant: k-block j lives in buffer j % STAGES.
// Safety of single sync: refill target (iter+2)%3 was last read at iter-1;
// the top sync of iter guarantees all warps finished iter-1's compute.
// ---------------------------------------------------------------------------
#define STAGES 3

__global__ __launch_bounds__(256, 2)
void gemm_tf32_kernel(const float* __restrict__ A,
                      const float* __restrict__ B,
                      const float* __restrict__ bias,
                      float* __restrict__ C,
                      int M, int N, int K) {
    __shared__ float As[STAGES][128][20];
    __shared__ float Bs[STAGES][16][136];

    const int tid  = threadIdx.x;
    const int w    = tid >> 5;
    const int lane = tid & 31;
    const int gid  = lane >> 2;
    const int tig  = lane & 3;
    const int wm   = w >> 2;
    const int wn   = w & 3;

    const int rowBase = blockIdx.y * 128;
    const int colBase = blockIdx.x * 128;

    const int a_row0 = tid >> 2,         a_kq0 = (tid & 3) << 2;
    const int a_row1 = (tid + 256) >> 2, a_kq1 = ((tid + 256) & 3) << 2;
    const int b_row0 = tid >> 5,         b_nq0 = (tid & 31) << 2;
    const int b_row1 = (tid + 256) >> 5, b_nq1 = ((tid + 256) & 31) << 2;

    float acc[4][4][4];
    #pragma unroll
    for (int mt = 0; mt < 4; mt++)
        #pragma unroll
        for (int nt = 0; nt < 4; nt++)
            #pragma unroll
            for (int r = 0; r < 4; r++) acc[mt][nt][r] = 0.0f;

    const int KITERS = K >> 4;

    #pragma unroll
    for (int s = 0; s < STAGES - 1; s++) {
        const int k0 = s << 4;
        cp_async16(&As[s][a_row0][a_kq0], &A[(size_t)(rowBase + a_row0) * K + k0 + a_kq0]);
        cp_async16(&As[s][a_row1][a_kq1], &A[(size_t)(rowBase + a_row1) * K + k0 + a_kq1]);
        cp_async16(&Bs[s][b_row0][b_nq0], &B[(size_t)(k0 + b_row0) * N + colBase + b_nq0]);
        cp_async16(&Bs[s][b_row1][b_nq1], &B[(size_t)(k0 + b_row1) * N + colBase + b_nq1]);
        cp_async_commit();
    }

    for (int iter = 0; iter < KITERS; iter++) {
        const int buf = iter % STAGES;
        cp_async_wait<STAGES - 2>();
        __syncthreads();

        // Refill first (overlaps with compute below)
        const int kload = iter + STAGES - 1;
        if (kload < KITERS) {
            const int sbuf = kload % STAGES;
            const int k0 = kload << 4;
            cp_async16(&As[sbuf][a_row0][a_kq0], &A[(size_t)(rowBase + a_row0) * K + k0 + a_kq0]);
            cp_async16(&As[sbuf][a_row1][a_kq1], &A[(size_t)(rowBase + a_row1) * K + k0 + a_kq1]);
            cp_async16(&Bs[sbuf][b_row0][b_nq0], &B[(size_t)(k0 + b_row0) * N + colBase + b_nq0]);
            cp_async16(&Bs[sbuf][b_row1][b_nq1], &B[(size_t)(k0 + b_row1) * N + colBase + b_nq1]);
        }
        cp_async_commit();

        #pragma unroll
        for (int kk = 0; kk < 2; kk++) {
            const int kb = kk * 8;
            uint32_t afr[4][4], bfr[4][2];
            #pragma unroll
            for (int mt = 0; mt < 4; mt++) {
                int m = wm * 64 + mt * 16;
                afr[mt][0] = f2tf32(As[buf][m + gid    ][kb + tig    ]);
                afr[mt][1] = f2tf32(As[buf][m + gid + 8][kb + tig    ]);
                afr[mt][2] = f2tf32(As[buf][m + gid    ][kb + tig + 4]);
                afr[mt][3] = f2tf32(As[buf][m + gid + 8][kb + tig + 4]);
            }
            #pragma unroll
            for (int nt = 0; nt < 4; nt++) {
                int n = wn * 32 + nt * 8;
                bfr[nt][0] = f2tf32(Bs[buf][kb + tig    ][n + gid]);
                bfr[nt][1] = f2tf32(Bs[buf][kb + tig + 4][n + gid]);
            }
            #pragma unroll
            for (int mt = 0; mt < 4; mt++)
                #pragma unroll
                for (int nt = 0; nt < 4; nt++)
                    mma_tf32(acc[mt][nt], afr[mt], bfr[nt]);
        }
    }

    #pragma unroll
    for (int mt = 0; mt < 4; mt++) {
        int r0 = rowBase + wm * 64 + mt * 16 + gid;
        #pragma unroll
        for (int nt = 0; nt < 4; nt++) {
            int c0 = colBase + wn * 32 + nt * 8 + 2 * tig;
            float bi0 = bias[c0], bi1 = bias[c0 + 1];
            float2 v0 = make_float2(acc[mt][nt][0] + bi0, acc[mt][nt][1] + bi1);
            float2 v1 = make_float2(acc[mt][nt][2] + bi0, acc[mt][nt][3] + bi1);
            *reinterpret_cast<float2*>(&C[(size_t)r0       * N + c0]) = v0;
            *reinterpret_cast<float2*>(&C[(size_t)(r0 + 8) * N + c0]) = v1;
        }
    }
}

// ---------------------------------------------------------------------------
// tf32 TC flash attention (causal), double-buffered cp.async K/V,
// shuffle-based P fragment conversion (no P smem), 1 sync per tile.
// Ks stride 68 (banks 4*gid+tig, conflict-free), Vs stride 72 (banks
// 8*tig+gid, conflict-free — fixes R2's 4-way conflict).
// Dynamic smem: 2*64*68*4 + 2*64*72*4 = 71680 B.
// ---------------------------------------------------------------------------
#define KS_F (64 * 68)
#define VS_F (64 * 72)
#define ATTN_SMEM ((2 * KS_F + 2 * VS_F) * 4)

__global__ __launch_bounds__(128, 3)
void attn_tf32_kernel() {
    extern __shared__ float sm[];
    float* KsB = sm;                 // [2][64][68]
    float* VsB = sm + 2 * KS_F;      // [2][64][72]

    const int qt = gridDim.x - 1 - blockIdx.x;   // heavy CTAs first
    const int h  = blockIdx.y;
    const int b  = blockIdx.z;

    const int tid  = threadIdx.x;
    const int warp = tid >> 5;
    const int lane = tid & 31;
    const int gid  = lane >> 2;
    const int tig  = lane & 3;
    const int wrow = warp * 16;
    const int qrow0 = qt * 64;
    const float scale = 0.125f;

    // Hoist Q fragments
    uint32_t qf[8][4];
    {
        const float* Qb = g_qkv + (size_t)(b * LSEQ + qrow0 + wrow) * 3072 + h * 64;
        #pragma unroll
        for (int kc = 0; kc < 8; kc++) {
            qf[kc][0] = f2tf32(Qb[(size_t)gid       * 3072 + kc * 8 + tig    ]);
            qf[kc][1] = f2tf32(Qb[(size_t)(gid + 8) * 3072 + kc * 8 + tig    ]);
            qf[kc][2] = f2tf32(Qb[(size_t)gid       * 3072 + kc * 8 + tig + 4]);
            qf[kc][3] = f2tf32(Qb[(size_t)(gid + 8) * 3072 + kc * 8 + tig + 4]);
        }
    }

    float o[8][4];
    #pragma unroll
    for (int nt = 0; nt < 8; nt++)
        #pragma unroll
        for (int j = 0; j < 4; j++) o[nt][j] = 0.0f;
    float m0 = -1e30f, m8 = -1e30f, l0 = 0.0f, l8 = 0.0f;

    // Tile loader: 64x64 fp32 K and V, 16B chunks, 8+8 per thread
    auto load_tile = [&](int kt, int buf) {
        const float* base = g_qkv + (size_t)(b * LSEQ + kt * 64) * 3072 + h * 64;
        float* kd = KsB + buf * KS_F;
        float* vd = VsB + buf * VS_F;
        #pragma unroll
        for (int c = tid; c < 1024; c += 128) {
            int r = c >> 4, c4 = (c & 15) << 2;
            const float* src = base + (size_t)r * 3072 + c4;
            cp_async16(kd + r * 68 + c4, src + 1024);
            cp_async16(vd + r * 72 + c4, src + 2048);
        }
    };

    load_tile(0, 0);
    cp_async_commit();

    for (int kt = 0; kt <= qt; kt++) {
        const int buf = kt & 1;
        cp_async_wait<0>();
        __syncthreads();            // tile kt ready; all warps done with buf^1

        if (kt < qt) load_tile(kt + 1, buf ^ 1);
        cp_async_commit();

        const float* Kb = KsB + buf * KS_F;
        const float* Vb = VsB + buf * VS_F;

        // S = Q @ K^T
        float s[8][4];
        #pragma unroll
        for (int nt = 0; nt < 8; nt++)
            #pragma unroll
            for (int j = 0; j < 4; j++) s[nt][j] = 0.0f;

        #pragma unroll
        for (int kc = 0; kc < 8; kc++) {
            #pragma unroll
            for (int nt = 0; nt < 8; nt++) {
                uint32_t bfr[2];
                bfr[0] = f2tf32(Kb[(nt * 8 + gid) * 68 + kc * 8 + tig    ]);
                bfr[1] = f2tf32(Kb[(nt * 8 + gid) * 68 + kc * 8 + tig + 4]);
                mma_tf32(s[nt], qf[kc], bfr);
            }
        }

        #pragma unroll
        for (int nt = 0; nt < 8; nt++)
            #pragma unroll
            for (int j = 0; j < 4; j++) s[nt][j] *= scale;

        if (kt == qt) {
            const int r0 = wrow + gid, r8 = r0 + 8;
            #pragma unroll
            for (int nt = 0; nt < 8; nt++) {
                int c = nt * 8 + 2 * tig;
                if (c     > r0) s[nt][0] = -1e30f;
                if (c + 1 > r0) s[nt][1] = -1e30f;
                if (c     > r8) s[nt][2] = -1e30f;
                if (c + 1 > r8) s[nt][3] = -1e30f;
            }
        }

        // Online softmax; p values stay in s[][]
        float mt0 = -1e30f, mt8 = -1e30f;
        #pragma unroll
        for (int nt = 0; nt < 8; nt++) {
            mt0 = fmaxf(mt0, fmaxf(s[nt][0], s[nt][1]));
            mt8 = fmaxf(mt8, fmaxf(s[nt][2], s[nt][3]));
        }
        #pragma unroll
        for (int off = 1; off < 4; off <<= 1) {
            mt0 = fmaxf(mt0, __shfl_xor_sync(0xffffffffu, mt0, off));
            mt8 = fmaxf(mt8, __shfl_xor_sync(0xffffffffu, mt8, off));
        }
        const float mn0 = fmaxf(m0, mt0), mn8 = fmaxf(m8, mt8);
        const float a0 = __expf(m0 - mn0), a8 = __expf(m8 - mn8);

        float rs0 = 0.0f, rs8 = 0.0f;
        #pragma unroll
        for (int nt = 0; nt < 8; nt++) {
            s[nt][0] = __expf(s[nt][0] - mn0);
            s[nt][1] = __expf(s[nt][1] - mn0);
            s[nt][2] = __expf(s[nt][2] - mn8);
            s[nt][3] = __expf(s[nt][3] - mn8);
            rs0 += s[nt][0] + s[nt][1];
            rs8 += s[nt][2] + s[nt][3];
            o[nt][0] *= a0; o[nt][1] *= a0;
            o[nt][2] *= a8; o[nt][3] *= a8;
        }
        #pragma unroll
        for (int off = 1; off < 4; off <<= 1) {
            rs0 += __shfl_xor_sync(0xffffffffu, rs0, off);
            rs8 += __shfl_xor_sync(0xffffffffu, rs8, off);
        }
        l0 = l0 * a0 + rs0;
        l8 = l8 * a8 + rs8;
        m0 = mn0; m8 = mn8;

        // O += P @ V : A-fragment from C-fragment via shuffles (no smem P).
        // Col j of block kc lives in lane (4*gid + j/2), element j&1.
        const int src0 = (lane & 0x1C) | (tig >> 1);   // col tig
        const int src1 = src0 + 2;                     // col tig+4
        const bool odd = tig & 1;
        #pragma unroll
        for (int kc = 0; kc < 8; kc++) {
            float v00 = __shfl_sync(0xffffffffu, s[kc][0], src0);
            float v01 = __shfl_sync(0xffffffffu, s[kc][1], src0);
            float v20 = __shfl_sync(0xffffffffu, s[kc][2], src0);
            float v31 = __shfl_sync(0xffffffffu, s[kc][3], src0);
            float w00 = __shfl_sync(0xffffffffu, s[kc][0], src1);
            float w01 = __shfl_sync(0xffffffffu, s[kc][1], src1);
            float w20 = __shfl_sync(0xffffffffu, s[kc][2], src1);
            float w31 = __shfl_sync(0xffffffffu, s[kc][3], src1);
            uint32_t af[4];
            af[0] = f2tf32(odd ? v01 : v00);   // P[gid  ][kc*8+tig  ]
            af[1] = f2tf32(odd ? v31 : v20);   // P[gid+8][kc*8+tig  ]
            af[2] = f2tf32(odd ? w01 : w00);   // P[gid  ][kc*8+tig+4]
            af[3] = f2tf32(odd ? w31 : w20);   // P[gid+8][kc*8+tig+4]
            #pragma unroll
            for (int nt = 0; nt < 8; nt++) {
                uint32_t bfr[2];
                bfr[0] = f2tf32(Vb[(kc * 8 + tig    ) * 72 + nt * 8 + gid]);
                bfr[1] = f2tf32(Vb[(kc * 8 + tig + 4) * 72 + nt * 8 + gid]);
                mma_tf32(o[nt], af, bfr);
            }
        }
    }

    const float inv0 = 1.0f / l0, inv8 = 1.0f / l8;
    float* dst = g_attn + (size_t)(b * LSEQ + qrow0 + wrow) * D_MODEL + h * 64;
    #pragma unroll
    for (int nt = 0; nt < 8; nt++) {
        int c = nt * 8 + 2 * tig;
        float2 v0 = make_float2(o[nt][0] * inv0, o[nt][1] * inv0);
        float2 v1 = make_float2(o[nt][2] * inv8, o[nt][3] * inv8);
        *reinterpret_cast<float2*>(dst + (size_t)gid       * D_MODEL + c) = v0;
        *reinterpret_cast<float2*>(dst + (size_t)(gid + 8) * D_MODEL + c) = v1;
    }
}

// ---------------------------------------------------------------------------
extern "C" void kernel_launch(void* const* d_in, const int* in_sizes, int n_in,
                              void* d_out, int out_size) {
    const float* x     = (const float*)d_in[0];
    const float* W_qkv = (const float*)d_in[1];
    const float* b_qkv = (const float*)d_in[2];
    const float* W_out = (const float*)d_in[3];
    const float* b_out = (const float*)d_in[4];
    float* out = (float*)d_out;

    float* qkv;  cudaGetSymbolAddress((void**)&qkv,  g_qkv);
    float* attn; cudaGetSymbolAddress((void**)&attn, g_attn);

    cudaFuncSetAttribute(attn_tf32_kernel,
                         cudaFuncAttributeMaxDynamicSharedMemorySize, ATTN_SMEM);

    dim3 g1(3 * D_MODEL / 128, NTOK / 128);
    gemm_tf32_kernel<<<g1, 256>>>(x, W_qkv, b_qkv, qkv, NTOK, 3 * D_MODEL, D_MODEL);

    dim3 g2(LSEQ / 64, NHEAD, NB);
    attn_tf32_kernel<<<g2, 128, ATTN_SMEM>>>();

    dim3 g3(D_MODEL / 128, NTOK / 128);
    gemm_tf32_kernel<<<g3, 256>>>(attn, W_out, b_out, out, NTOK, D_MODEL, D_MODEL);
}

// round 7
// speedup vs baseline: 1.0750x; 1.0750x over previous
#include <cuda_runtime.h>
#include <cstdint>

#define D_MODEL 1024
#define LSEQ    2048
#define NB      2
#define NHEAD   16
#define HD      64
#define NTOK    (NB * LSEQ)   // 4096

__device__ float g_qkv[(size_t)NTOK * 3 * D_MODEL];   // [4096, 3072]
__device__ float g_attn[(size_t)NTOK * D_MODEL];      // [4096, 1024] = [B,L,H,hd]

// ---------------------------------------------------------------------------
// tf32 helpers
// ---------------------------------------------------------------------------
__device__ __forceinline__ uint32_t f2tf32(float f) {
    uint32_t r;
    asm("cvt.rna.tf32.f32 %0, %1;" : "=r"(r) : "f"(f));
    return r;
}

__device__ __forceinline__ void mma_tf32(float c[4], const uint32_t a[4], const uint32_t b[2]) {
    asm volatile(
        "mma.sync.aligned.m16n8k8.row.col.f32.tf32.tf32.f32 "
        "{%0,%1,%2,%3}, {%4,%5,%6,%7}, {%8,%9}, {%0,%1,%2,%3};"
        : "+f"(c[0]), "+f"(c[1]), "+f"(c[2]), "+f"(c[3])
        : "r"(a[0]), "r"(a[1]), "r"(a[2]), "r"(a[3]),
          "r"(b[0]), "r"(b[1]));
}

__device__ __forceinline__ void cp_async16(void* smem_dst, const void* gmem_src) {
    uint32_t dst;
    asm("{ .reg .u64 t; cvta.to.shared.u64 t, %1; cvt.u32.u64 %0, t; }"
        : "=r"(dst) : "l"(smem_dst));
    asm volatile("cp.async.cg.shared.global [%0], [%1], 16;" :: "r"(dst), "l"(gmem_src));
}
__device__ __forceinline__ void cp_async_commit() {
    asm volatile("cp.async.commit_group;");
}
template <int N>
__device__ __forceinline__ void cp_async_wait() {
    asm volatile("cp.async.wait_group %0;" :: "n"(N));
}

// ---------------------------------------------------------------------------
// tf32 tensor-core GEMM, 3-stage cp.async pipeline — R4 ordering (measured
// 207us): compute -> sync -> refill. (R5's refill-first + single-sync
// variant measured 235us; reverted.)
// Invariant: k-block j lives in buffer j % STAGES.
// ---------------------------------------------------------------------------
#define STAGES 3

__global__ __launch_bounds__(256, 2)
void gemm_tf32_kernel(const float* __restrict__ A,
                      const float* __restrict__ B,
                      const float* __restrict__ bias,
                      float* __restrict__ C,
                      int M, int N, int K) {
    __shared__ float As[STAGES][128][20];
    __shared__ float Bs[STAGES][16][136];

    const int tid  = threadIdx.x;
    const int w    = tid >> 5;
    const int lane = tid & 31;
    const int gid  = lane >> 2;
    const int tig  = lane & 3;
    const int wm   = w >> 2;
    const int wn   = w & 3;

    const int rowBase = blockIdx.y * 128;
    const int colBase = blockIdx.x * 128;

    const int a_row0 = tid >> 2,         a_kq0 = (tid & 3) << 2;
    const int a_row1 = (tid + 256) >> 2, a_kq1 = ((tid + 256) & 3) << 2;
    const int b_row0 = tid >> 5,         b_nq0 = (tid & 31) << 2;
    const int b_row1 = (tid + 256) >> 5, b_nq1 = ((tid + 256) & 31) << 2;

    float acc[4][4][4];
    #pragma unroll
    for (int mt = 0; mt < 4; mt++)
        #pragma unroll
        for (int nt = 0; nt < 4; nt++)
            #pragma unroll
            for (int r = 0; r < 4; r++) acc[mt][nt][r] = 0.0f;

    const int KITERS = K >> 4;

    #pragma unroll
    for (int s = 0; s < STAGES - 1; s++) {
        const int k0 = s << 4;
        cp_async16(&As[s][a_row0][a_kq0], &A[(size_t)(rowBase + a_row0) * K + k0 + a_kq0]);
        cp_async16(&As[s][a_row1][a_kq1], &A[(size_t)(rowBase + a_row1) * K + k0 + a_kq1]);
        cp_async16(&Bs[s][b_row0][b_nq0], &B[(size_t)(k0 + b_row0) * N + colBase + b_nq0]);
        cp_async16(&Bs[s][b_row1][b_nq1], &B[(size_t)(k0 + b_row1) * N + colBase + b_nq1]);
        cp_async_commit();
    }

    for (int iter = 0; iter < KITERS; iter++) {
        const int buf = iter % STAGES;
        cp_async_wait<STAGES - 2>();
        __syncthreads();

        #pragma unroll
        for (int kk = 0; kk < 2; kk++) {
            const int kb = kk * 8;
            uint32_t afr[4][4], bfr[4][2];
            #pragma unroll
            for (int mt = 0; mt < 4; mt++) {
                int m = wm * 64 + mt * 16;
                afr[mt][0] = f2tf32(As[buf][m + gid    ][kb + tig    ]);
                afr[mt][1] = f2tf32(As[buf][m + gid + 8][kb + tig    ]);
                afr[mt][2] = f2tf32(As[buf][m + gid    ][kb + tig + 4]);
                afr[mt][3] = f2tf32(As[buf][m + gid + 8][kb + tig + 4]);
            }
            #pragma unroll
            for (int nt = 0; nt < 4; nt++) {
                int n = wn * 32 + nt * 8;
                bfr[nt][0] = f2tf32(Bs[buf][kb + tig    ][n + gid]);
                bfr[nt][1] = f2tf32(Bs[buf][kb + tig + 4][n + gid]);
            }
            #pragma unroll
            for (int mt = 0; mt < 4; mt++)
                #pragma unroll
                for (int nt = 0; nt < 4; nt++)
                    mma_tf32(acc[mt][nt], afr[mt], bfr[nt]);
        }
        __syncthreads();   // all warps done with oldest buffers before refill

        const int kload = iter + STAGES - 1;
        if (kload < KITERS) {
            const int sbuf = kload % STAGES;
            const int k0 = kload << 4;
            cp_async16(&As[sbuf][a_row0][a_kq0], &A[(size_t)(rowBase + a_row0) * K + k0 + a_kq0]);
            cp_async16(&As[sbuf][a_row1][a_kq1], &A[(size_t)(rowBase + a_row1) * K + k0 + a_kq1]);
            cp_async16(&Bs[sbuf][b_row0][b_nq0], &B[(size_t)(k0 + b_row0) * N + colBase + b_nq0]);
            cp_async16(&Bs[sbuf][b_row1][b_nq1], &B[(size_t)(k0 + b_row1) * N + colBase + b_nq1]);
        }
        cp_async_commit();
    }

    #pragma unroll
    for (int mt = 0; mt < 4; mt++) {
        int r0 = rowBase + wm * 64 + mt * 16 + gid;
        #pragma unroll
        for (int nt = 0; nt < 4; nt++) {
            int c0 = colBase + wn * 32 + nt * 8 + 2 * tig;
            float bi0 = bias[c0], bi1 = bias[c0 + 1];
            float2 v0 = make_float2(acc[mt][nt][0] + bi0, acc[mt][nt][1] + bi1);
            float2 v1 = make_float2(acc[mt][nt][2] + bi0, acc[mt][nt][3] + bi1);
            *reinterpret_cast<float2*>(&C[(size_t)r0       * N + c0]) = v0;
            *reinterpret_cast<float2*>(&C[(size_t)(r0 + 8) * N + c0]) = v1;
        }
    }
}

// ---------------------------------------------------------------------------
// tf32 TC flash attention (causal) — R5 version (measured ~209us, kept).
// Double-buffered cp.async K/V, shuffle-based P fragment conversion,
// 1 sync per tile, conflict-free Ks (stride 68) / Vs (stride 72).
// ---------------------------------------------------------------------------
#define KS_F (64 * 68)
#define VS_F (64 * 72)
#define ATTN_SMEM ((2 * KS_F + 2 * VS_F) * 4)

__global__ __launch_bounds__(128, 3)
void attn_tf32_kernel() {
    extern __shared__ float sm[];
    float* KsB = sm;                 // [2][64][68]
    float* VsB = sm + 2 * KS_F;      // [2][64][72]

    const int qt = gridDim.x - 1 - blockIdx.x;   // heavy CTAs first
    const int h  = blockIdx.y;
    const int b  = blockIdx.z;

    const int tid  = threadIdx.x;
    const int warp = tid >> 5;
    const int lane = tid & 31;
    const int gid  = lane >> 2;
    const int tig  = lane & 3;
    const int wrow = warp * 16;
    const int qrow0 = qt * 64;
    const float scale = 0.125f;

    uint32_t qf[8][4];
    {
        const float* Qb = g_qkv + (size_t)(b * LSEQ + qrow0 + wrow) * 3072 + h * 64;
        #pragma unroll
        for (int kc = 0; kc < 8; kc++) {
            qf[kc][0] = f2tf32(Qb[(size_t)gid       * 3072 + kc * 8 + tig    ]);
            qf[kc][1] = f2tf32(Qb[(size_t)(gid + 8) * 3072 + kc * 8 + tig    ]);
            qf[kc][2] = f2tf32(Qb[(size_t)gid       * 3072 + kc * 8 + tig + 4]);
            qf[kc][3] = f2tf32(Qb[(size_t)(gid + 8) * 3072 + kc * 8 + tig + 4]);
        }
    }

    float o[8][4];
    #pragma unroll
    for (int nt = 0; nt < 8; nt++)
        #pragma unroll
        for (int j = 0; j < 4; j++) o[nt][j] = 0.0f;
    float m0 = -1e30f, m8 = -1e30f, l0 = 0.0f, l8 = 0.0f;

    auto load_tile = [&](int kt, int buf) {
        const float* base = g_qkv + (size_t)(b * LSEQ + kt * 64) * 3072 + h * 64;
        float* kd = KsB + buf * KS_F;
        float* vd = VsB + buf * VS_F;
        #pragma unroll
        for (int c = tid; c < 1024; c += 128) {
            int r = c >> 4, c4 = (c & 15) << 2;
            const float* src = base + (size_t)r * 3072 + c4;
            cp_async16(kd + r * 68 + c4, src + 1024);
            cp_async16(vd + r * 72 + c4, src + 2048);
        }
    };

    load_tile(0, 0);
    cp_async_commit();

    for (int kt = 0; kt <= qt; kt++) {
        const int buf = kt & 1;
        cp_async_wait<0>();
        __syncthreads();

        if (kt < qt) load_tile(kt + 1, buf ^ 1);
        cp_async_commit();

        const float* Kb = KsB + buf * KS_F;
        const float* Vb = VsB + buf * VS_F;

        float s[8][4];
        #pragma unroll
        for (int nt = 0; nt < 8; nt++)
            #pragma unroll
            for (int j = 0; j < 4; j++) s[nt][j] = 0.0f;

        #pragma unroll
        for (int kc = 0; kc < 8; kc++) {
            #pragma unroll
            for (int nt = 0; nt < 8; nt++) {
                uint32_t bfr[2];
                bfr[0] = f2tf32(Kb[(nt * 8 + gid) * 68 + kc * 8 + tig    ]);
                bfr[1] = f2tf32(Kb[(nt * 8 + gid) * 68 + kc * 8 + tig + 4]);
                mma_tf32(s[nt], qf[kc], bfr);
            }
        }

        #pragma unroll
        for (int nt = 0; nt < 8; nt++)
            #pragma unroll
            for (int j = 0; j < 4; j++) s[nt][j] *= scale;

        if (kt == qt) {
            const int r0 = wrow + gid, r8 = r0 + 8;
            #pragma unroll
            for (int nt = 0; nt < 8; nt++) {
                int c = nt * 8 + 2 * tig;
                if (c     > r0) s[nt][0] = -1e30f;
                if (c + 1 > r0) s[nt][1] = -1e30f;
                if (c     > r8) s[nt][2] = -1e30f;
                if (c + 1 > r8) s[nt][3] = -1e30f;
            }
        }

        float mt0 = -1e30f, mt8 = -1e30f;
        #pragma unroll
        for (int nt = 0; nt < 8; nt++) {
            mt0 = fmaxf(mt0, fmaxf(s[nt][0], s[nt][1]));
            mt8 = fmaxf(mt8, fmaxf(s[nt][2], s[nt][3]));
        }
        #pragma unroll
        for (int off = 1; off < 4; off <<= 1) {
            mt0 = fmaxf(mt0, __shfl_xor_sync(0xffffffffu, mt0, off));
            mt8 = fmaxf(mt8, __shfl_xor_sync(0xffffffffu, mt8, off));
        }
        const float mn0 = fmaxf(m0, mt0), mn8 = fmaxf(m8, mt8);
        const float a0 = __expf(m0 - mn0), a8 = __expf(m8 - mn8);

        float rs0 = 0.0f, rs8 = 0.0f;
        #pragma unroll
        for (int nt = 0; nt < 8; nt++) {
            s[nt][0] = __expf(s[nt][0] - mn0);
            s[nt][1] = __expf(s[nt][1] - mn0);
            s[nt][2] = __expf(s[nt][2] - mn8);
            s[nt][3] = __expf(s[nt][3] - mn8);
            rs0 += s[nt][0] + s[nt][1];
            rs8 += s[nt][2] + s[nt][3];
            o[nt][0] *= a0; o[nt][1] *= a0;
            o[nt][2] *= a8; o[nt][3] *= a8;
        }
        #pragma unroll
        for (int off = 1; off < 4; off <<= 1) {
            rs0 += __shfl_xor_sync(0xffffffffu, rs0, off);
            rs8 += __shfl_xor_sync(0xffffffffu, rs8, off);
        }
        l0 = l0 * a0 + rs0;
        l8 = l8 * a8 + rs8;
        m0 = mn0; m8 = mn8;

        const int src0 = (lane & 0x1C) | (tig >> 1);
        const int src1 = src0 + 2;
        const bool odd = tig & 1;
        #pragma unroll
        for (int kc = 0; kc < 8; kc++) {
            float v00 = __shfl_sync(0xffffffffu, s[kc][0], src0);
            float v01 = __shfl_sync(0xffffffffu, s[kc][1], src0);
            float v20 = __shfl_sync(0xffffffffu, s[kc][2], src0);
            float v31 = __shfl_sync(0xffffffffu, s[kc][3], src0);
            float w00 = __shfl_sync(0xffffffffu, s[kc][0], src1);
            float w01 = __shfl_sync(0xffffffffu, s[kc][1], src1);
            float w20 = __shfl_sync(0xffffffffu, s[kc][2], src1);
            float w31 = __shfl_sync(0xffffffffu, s[kc][3], src1);
            uint32_t af[4];
            af[0] = f2tf32(odd ? v01 : v00);
            af[1] = f2tf32(odd ? v31 : v20);
            af[2] = f2tf32(odd ? w01 : w00);
            af[3] = f2tf32(odd ? w31 : w20);
            #pragma unroll
            for (int nt = 0; nt < 8; nt++) {
                uint32_t bfr[2];
                bfr[0] = f2tf32(Vb[(kc * 8 + tig    ) * 72 + nt * 8 + gid]);
                bfr[1] = f2tf32(Vb[(kc * 8 + tig + 4) * 72 + nt * 8 + gid]);
                mma_tf32(o[nt], af, bfr);
            }
        }
    }

    const float inv0 = 1.0f / l0, inv8 = 1.0f / l8;
    float* dst = g_attn + (size_t)(b * LSEQ + qrow0 + wrow) * D_MODEL + h * 64;
    #pragma unroll
    for (int nt = 0; nt < 8; nt++) {
        int c = nt * 8 + 2 * tig;
        float2 v0 = make_float2(o[nt][0] * inv0, o[nt][1] * inv0);
        float2 v1 = make_float2(o[nt][2] * inv8, o[nt][3] * inv8);
        *reinterpret_cast<float2*>(dst + (size_t)gid       * D_MODEL + c) = v0;
        *reinterpret_cast<float2*>(dst + (size_t)(gid + 8) * D_MODEL + c) = v1;
    }
}

// ---------------------------------------------------------------------------
extern "C" void kernel_launch(void* const* d_in, const int* in_sizes, int n_in,
                              void* d_out, int out_size) {
    const float* x     = (const float*)d_in[0];
    const float* W_qkv = (const float*)d_in[1];
    const float* b_qkv = (const float*)d_in[2];
    const float* W_out = (const float*)d_in[3];
    const float* b_out = (const float*)d_in[4];
    float* out = (float*)d_out;

    float* qkv;  cudaGetSymbolAddress((void**)&qkv,  g_qkv);
    float* attn; cudaGetSymbolAddress((void**)&attn, g_attn);

    cudaFuncSetAttribute(attn_tf32_kernel,
                         cudaFuncAttributeMaxDynamicSharedMemorySize, ATTN_SMEM);

    dim3 g1(3 * D_MODEL / 128, NTOK / 128);
    gemm_tf32_kernel<<<g1, 256>>>(x, W_qkv, b_qkv, qkv, NTOK, 3 * D_MODEL, D_MODEL);

    dim3 g2(LSEQ / 64, NHEAD, NB);
    attn_tf32_kernel<<<g2, 128, ATTN_SMEM>>>();

    dim3 g3(D_MODEL / 128, NTOK / 128);
    gemm_tf32_kernel<<<g3, 256>>>(attn, W_out, b_out, out, NTOK, D_MODEL, D_MODEL);
}

// round 8
// speedup vs baseline: 1.1100x; 1.0326x over previous
#include <cuda_runtime.h>
#include <cstdint>

#define D_MODEL 1024
#define LSEQ    2048
#define NB      2
#define NHEAD   16
#define HD      64
#define NTOK    (NB * LSEQ)   // 4096

// Scratch (device globals — alloc-free per harness rules)
__device__ float g_qkv[(size_t)NTOK * 3 * D_MODEL];    // [4096, 3072] (tf32-rounded)
__device__ float g_attn[(size_t)NTOK * D_MODEL];       // [4096, 1024] (tf32-rounded)
__device__ float g_xr[(size_t)NTOK * D_MODEL];         // x, tf32-rounded
__device__ float g_wqkvr[(size_t)D_MODEL * 3 * D_MODEL]; // W_qkv, tf32-rounded
__device__ float g_woutr[(size_t)D_MODEL * D_MODEL];   // W_out, tf32-rounded

// ---------------------------------------------------------------------------
// tf32 helpers
// ---------------------------------------------------------------------------
__device__ __forceinline__ uint32_t f2tf32(float f) {
    uint32_t r;
    asm("cvt.rna.tf32.f32 %0, %1;" : "=r"(r) : "f"(f));
    return r;
}

__device__ __forceinline__ void mma_tf32(float c[4], const uint32_t a[4], const uint32_t b[2]) {
    asm volatile(
        "mma.sync.aligned.m16n8k8.row.col.f32.tf32.tf32.f32 "
        "{%0,%1,%2,%3}, {%4,%5,%6,%7}, {%8,%9}, {%0,%1,%2,%3};"
        : "+f"(c[0]), "+f"(c[1]), "+f"(c[2]), "+f"(c[3])
        : "r"(a[0]), "r"(a[1]), "r"(a[2]), "r"(a[3]),
          "r"(b[0]), "r"(b[1]));
}

__device__ __forceinline__ void cp_async16(void* smem_dst, const void* gmem_src) {
    uint32_t dst;
    asm("{ .reg .u64 t; cvta.to.shared.u64 t, %1; cvt.u32.u64 %0, t; }"
        : "=r"(dst) : "l"(smem_dst));
    asm volatile("cp.async.cg.shared.global [%0], [%1], 16;" :: "r"(dst), "l"(gmem_src));
}
__device__ __forceinline__ void cp_async_commit() {
    asm volatile("cp.async.commit_group;");
}
template <int N>
__device__ __forceinline__ void cp_async_wait() {
    asm volatile("cp.async.wait_group %0;" :: "n"(N));
}

// ---------------------------------------------------------------------------
// Prep: round fp32 array to tf32 (RNA) — preserves all rounding points that
// were previously applied at fragment-load time.
// ---------------------------------------------------------------------------
__global__ void round_tf32_kernel(const float* __restrict__ src,
                                  float* __restrict__ dst, int n4) {
    int i = blockIdx.x * blockDim.x + threadIdx.x;
    if (i < n4) {
        float4 v = reinterpret_cast<const float4*>(src)[i];
        uint4 r;
        r.x = f2tf32(v.x); r.y = f2tf32(v.y);
        r.z = f2tf32(v.z); r.w = f2tf32(v.w);
        reinterpret_cast<uint4*>(dst)[i] = r;
    }
}

// ---------------------------------------------------------------------------
// tf32 tensor-core GEMM, 3-stage cp.async pipeline, R4 ordering (proven).
// Inputs A, B are PRE-ROUNDED to tf32 — fragments are raw bit loads (no CVT).
// ROUND_OUT: round the (acc+bias) result to tf32 at store (moves the
// consumer's load-time rounding into this epilogue; numerics identical).
// ---------------------------------------------------------------------------
#define STAGES 3

template <bool ROUND_OUT>
__global__ __launch_bounds__(256, 2)
void gemm_tf32_kernel(const float* __restrict__ A,
                      const float* __restrict__ B,
                      const float* __restrict__ bias,
                      float* __restrict__ C,
                      int M, int N, int K) {
    __shared__ float As[STAGES][128][20];
    __shared__ float Bs[STAGES][16][136];

    const int tid  = threadIdx.x;
    const int w    = tid >> 5;
    const int lane = tid & 31;
    const int gid  = lane >> 2;
    const int tig  = lane & 3;
    const int wm   = w >> 2;
    const int wn   = w & 3;

    const int rowBase = blockIdx.y * 128;
    const int colBase = blockIdx.x * 128;

    const int a_row0 = tid >> 2,         a_kq0 = (tid & 3) << 2;
    const int a_row1 = (tid + 256) >> 2, a_kq1 = ((tid + 256) & 3) << 2;
    const int b_row0 = tid >> 5,         b_nq0 = (tid & 31) << 2;
    const int b_row1 = (tid + 256) >> 5, b_nq1 = ((tid + 256) & 31) << 2;

    float acc[4][4][4];
    #pragma unroll
    for (int mt = 0; mt < 4; mt++)
        #pragma unroll
        for (int nt = 0; nt < 4; nt++)
            #pragma unroll
            for (int r = 0; r < 4; r++) acc[mt][nt][r] = 0.0f;

    const int KITERS = K >> 4;

    #pragma unroll
    for (int s = 0; s < STAGES - 1; s++) {
        const int k0 = s << 4;
        cp_async16(&As[s][a_row0][a_kq0], &A[(size_t)(rowBase + a_row0) * K + k0 + a_kq0]);
        cp_async16(&As[s][a_row1][a_kq1], &A[(size_t)(rowBase + a_row1) * K + k0 + a_kq1]);
        cp_async16(&Bs[s][b_row0][b_nq0], &B[(size_t)(k0 + b_row0) * N + colBase + b_nq0]);
        cp_async16(&Bs[s][b_row1][b_nq1], &B[(size_t)(k0 + b_row1) * N + colBase + b_nq1]);
        cp_async_commit();
    }

    for (int iter = 0; iter < KITERS; iter++) {
        const int buf = iter % STAGES;
        cp_async_wait<STAGES - 2>();
        __syncthreads();

        #pragma unroll
        for (int kk = 0; kk < 2; kk++) {
            const int kb = kk * 8;
            uint32_t afr[4][4], bfr[4][2];
            #pragma unroll
            for (int mt = 0; mt < 4; mt++) {
                int m = wm * 64 + mt * 16;
                afr[mt][0] = __float_as_uint(As[buf][m + gid    ][kb + tig    ]);
                afr[mt][1] = __float_as_uint(As[buf][m + gid + 8][kb + tig    ]);
                afr[mt][2] = __float_as_uint(As[buf][m + gid    ][kb + tig + 4]);
                afr[mt][3] = __float_as_uint(As[buf][m + gid + 8][kb + tig + 4]);
            }
            #pragma unroll
            for (int nt = 0; nt < 4; nt++) {
                int n = wn * 32 + nt * 8;
                bfr[nt][0] = __float_as_uint(Bs[buf][kb + tig    ][n + gid]);
                bfr[nt][1] = __float_as_uint(Bs[buf][kb + tig + 4][n + gid]);
            }
            #pragma unroll
            for (int mt = 0; mt < 4; mt++)
                #pragma unroll
                for (int nt = 0; nt < 4; nt++)
                    mma_tf32(acc[mt][nt], afr[mt], bfr[nt]);
        }
        __syncthreads();

        const int kload = iter + STAGES - 1;
        if (kload < KITERS) {
            const int sbuf = kload % STAGES;
            const int k0 = kload << 4;
            cp_async16(&As[sbuf][a_row0][a_kq0], &A[(size_t)(rowBase + a_row0) * K + k0 + a_kq0]);
            cp_async16(&As[sbuf][a_row1][a_kq1], &A[(size_t)(rowBase + a_row1) * K + k0 + a_kq1]);
            cp_async16(&Bs[sbuf][b_row0][b_nq0], &B[(size_t)(k0 + b_row0) * N + colBase + b_nq0]);
            cp_async16(&Bs[sbuf][b_row1][b_nq1], &B[(size_t)(k0 + b_row1) * N + colBase + b_nq1]);
        }
        cp_async_commit();
    }

    #pragma unroll
    for (int mt = 0; mt < 4; mt++) {
        int r0 = rowBase + wm * 64 + mt * 16 + gid;
        #pragma unroll
        for (int nt = 0; nt < 4; nt++) {
            int c0 = colBase + wn * 32 + nt * 8 + 2 * tig;
            float bi0 = bias[c0], bi1 = bias[c0 + 1];
            float r00 = acc[mt][nt][0] + bi0, r01 = acc[mt][nt][1] + bi1;
            float r10 = acc[mt][nt][2] + bi0, r11 = acc[mt][nt][3] + bi1;
            float2 v0, v1;
            if (ROUND_OUT) {
                v0 = make_float2(__uint_as_float(f2tf32(r00)), __uint_as_float(f2tf32(r01)));
                v1 = make_float2(__uint_as_float(f2tf32(r10)), __uint_as_float(f2tf32(r11)));
            } else {
                v0 = make_float2(r00, r01);
                v1 = make_float2(r10, r11);
            }
            *reinterpret_cast<float2*>(&C[(size_t)r0       * N + c0]) = v0;
            *reinterpret_cast<float2*>(&C[(size_t)(r0 + 8) * N + c0]) = v1;
        }
    }
}

// ---------------------------------------------------------------------------
// tf32 TC flash attention (causal) — R5 structure; Q/K/V now pre-rounded in
// g_qkv, so all fragment loads are raw bits (no CVT). P still rounds (f2tf32).
// Epilogue stores tf32-rounded output (out-proj consumes it raw).
// ---------------------------------------------------------------------------
#define KS_F (64 * 68)
#define VS_F (64 * 72)
#define ATTN_SMEM ((2 * KS_F + 2 * VS_F) * 4)

__global__ __launch_bounds__(128, 3)
void attn_tf32_kernel() {
    extern __shared__ float sm[];
    float* KsB = sm;                 // [2][64][68]
    float* VsB = sm + 2 * KS_F;      // [2][64][72]

    const int qt = gridDim.x - 1 - blockIdx.x;   // heavy CTAs first
    const int h  = blockIdx.y;
    const int b  = blockIdx.z;

    const int tid  = threadIdx.x;
    const int warp = tid >> 5;
    const int lane = tid & 31;
    const int gid  = lane >> 2;
    const int tig  = lane & 3;
    const int wrow = warp * 16;
    const int qrow0 = qt * 64;
    const float scale = 0.125f;

    uint32_t qf[8][4];
    {
        const float* Qb = g_qkv + (size_t)(b * LSEQ + qrow0 + wrow) * 3072 + h * 64;
        #pragma unroll
        for (int kc = 0; kc < 8; kc++) {
            qf[kc][0] = __float_as_uint(Qb[(size_t)gid       * 3072 + kc * 8 + tig    ]);
            qf[kc][1] = __float_as_uint(Qb[(size_t)(gid + 8) * 3072 + kc * 8 + tig    ]);
            qf[kc][2] = __float_as_uint(Qb[(size_t)gid       * 3072 + kc * 8 + tig + 4]);
            qf[kc][3] = __float_as_uint(Qb[(size_t)(gid + 8) * 3072 + kc * 8 + tig + 4]);
        }
    }

    float o[8][4];
    #pragma unroll
    for (int nt = 0; nt < 8; nt++)
        #pragma unroll
        for (int j = 0; j < 4; j++) o[nt][j] = 0.0f;
    float m0 = -1e30f, m8 = -1e30f, l0 = 0.0f, l8 = 0.0f;

    auto load_tile = [&](int kt, int buf) {
        const float* base = g_qkv + (size_t)(b * LSEQ + kt * 64) * 3072 + h * 64;
        float* kd = KsB + buf * KS_F;
        float* vd = VsB + buf * VS_F;
        #pragma unroll
        for (int c = tid; c < 1024; c += 128) {
            int r = c >> 4, c4 = (c & 15) << 2;
            const float* src = base + (size_t)r * 3072 + c4;
            cp_async16(kd + r * 68 + c4, src + 1024);
            cp_async16(vd + r * 72 + c4, src + 2048);
        }
    };

    load_tile(0, 0);
    cp_async_commit();

    for (int kt = 0; kt <= qt; kt++) {
        const int buf = kt & 1;
        cp_async_wait<0>();
        __syncthreads();

        if (kt < qt) load_tile(kt + 1, buf ^ 1);
        cp_async_commit();

        const float* Kb = KsB + buf * KS_F;
        const float* Vb = VsB + buf * VS_F;

        float s[8][4];
        #pragma unroll
        for (int nt = 0; nt < 8; nt++)
            #pragma unroll
            for (int j = 0; j < 4; j++) s[nt][j] = 0.0f;

        #pragma unroll
        for (int kc = 0; kc < 8; kc++) {
            #pragma unroll
            for (int nt = 0; nt < 8; nt++) {
                uint32_t bfr[2];
                bfr[0] = __float_as_uint(Kb[(nt * 8 + gid) * 68 + kc * 8 + tig    ]);
                bfr[1] = __float_as_uint(Kb[(nt * 8 + gid) * 68 + kc * 8 + tig + 4]);
                mma_tf32(s[nt], qf[kc], bfr);
            }
        }

        #pragma unroll
        for (int nt = 0; nt < 8; nt++)
            #pragma unroll
            for (int j = 0; j < 4; j++) s[nt][j] *= scale;

        if (kt == qt) {
            const int r0 = wrow + gid, r8 = r0 + 8;
            #pragma unroll
            for (int nt = 0; nt < 8; nt++) {
                int c = nt * 8 + 2 * tig;
                if (c     > r0) s[nt][0] = -1e30f;
                if (c + 1 > r0) s[nt][1] = -1e30f;
                if (c     > r8) s[nt][2] = -1e30f;
                if (c + 1 > r8) s[nt][3] = -1e30f;
            }
        }

        float mt0 = -1e30f, mt8 = -1e30f;
        #pragma unroll
        for (int nt = 0; nt < 8; nt++) {
            mt0 = fmaxf(mt0, fmaxf(s[nt][0], s[nt][1]));
            mt8 = fmaxf(mt8, fmaxf(s[nt][2], s[nt][3]));
        }
        #pragma unroll
        for (int off = 1; off < 4; off <<= 1) {
            mt0 = fmaxf(mt0, __shfl_xor_sync(0xffffffffu, mt0, off));
            mt8 = fmaxf(mt8, __shfl_xor_sync(0xffffffffu, mt8, off));
        }
        const float mn0 = fmaxf(m0, mt0), mn8 = fmaxf(m8, mt8);
        const float a0 = __expf(m0 - mn0), a8 = __expf(m8 - mn8);

        float rs0 = 0.0f, rs8 = 0.0f;
        #pragma unroll
        for (int nt = 0; nt < 8; nt++) {
            s[nt][0] = __expf(s[nt][0] - mn0);
            s[nt][1] = __expf(s[nt][1] - mn0);
            s[nt][2] = __expf(s[nt][2] - mn8);
            s[nt][3] = __expf(s[nt][3] - mn8);
            rs0 += s[nt][0] + s[nt][1];
            rs8 += s[nt][2] + s[nt][3];
            o[nt][0] *= a0; o[nt][1] *= a0;
            o[nt][2] *= a8; o[nt][3] *= a8;
        }
        #pragma unroll
        for (int off = 1; off < 4; off <<= 1) {
            rs0 += __shfl_xor_sync(0xffffffffu, rs0, off);
            rs8 += __shfl_xor_sync(0xffffffffu, rs8, off);
        }
        l0 = l0 * a0 + rs0;
        l8 = l8 * a8 + rs8;
        m0 = mn0; m8 = mn8;

        const int src0 = (lane & 0x1C) | (tig >> 1);
        const int src1 = src0 + 2;
        const bool odd = tig & 1;
        #pragma unroll
        for (int kc = 0; kc < 8; kc++) {
            float v00 = __shfl_sync(0xffffffffu, s[kc][0], src0);
            float v01 = __shfl_sync(0xffffffffu, s[kc][1], src0);
            float v20 = __shfl_sync(0xffffffffu, s[kc][2], src0);
            float v31 = __shfl_sync(0xffffffffu, s[kc][3], src0);
            float w00 = __shfl_sync(0xffffffffu, s[kc][0], src1);
            float w01 = __shfl_sync(0xffffffffu, s[kc][1], src1);
            float w20 = __shfl_sync(0xffffffffu, s[kc][2], src1);
            float w31 = __shfl_sync(0xffffffffu, s[kc][3], src1);
            uint32_t af[4];
            af[0] = f2tf32(odd ? v01 : v00);
            af[1] = f2tf32(odd ? v31 : v20);
            af[2] = f2tf32(odd ? w01 : w00);
            af[3] = f2tf32(odd ? w31 : w20);
            #pragma unroll
            for (int nt = 0; nt < 8; nt++) {
                uint32_t bfr[2];
                bfr[0] = __float_as_uint(Vb[(kc * 8 + tig    ) * 72 + nt * 8 + gid]);
                bfr[1] = __float_as_uint(Vb[(kc * 8 + tig + 4) * 72 + nt * 8 + gid]);
                mma_tf32(o[nt], af, bfr);
            }
        }
    }

    // Store tf32-rounded (out-proj consumes raw) — same rounding point as
    // the out-proj GEMM's previous load-time CVT.
    const float inv0 = 1.0f / l0, inv8 = 1.0f / l8;
    float* dst = g_attn + (size_t)(b * LSEQ + qrow0 + wrow) * D_MODEL + h * 64;
    #pragma unroll
    for (int nt = 0; nt < 8; nt++) {
        int c = nt * 8 + 2 * tig;
        float2 v0 = make_float2(__uint_as_float(f2tf32(o[nt][0] * inv0)),
                                __uint_as_float(f2tf32(o[nt][1] * inv0)));
        float2 v1 = make_float2(__uint_as_float(f2tf32(o[nt][2] * inv8)),
                                __uint_as_float(f2tf32(o[nt][3] * inv8)));
        *reinterpret_cast<float2*>(dst + (size_t)gid       * D_MODEL + c) = v0;
        *reinterpret_cast<float2*>(dst + (size_t)(gid + 8) * D_MODEL + c) = v1;
    }
}

// ---------------------------------------------------------------------------
extern "C" void kernel_launch(void* const* d_in, const int* in_sizes, int n_in,
                              void* d_out, int out_size) {
    const float* x     = (const float*)d_in[0];
    const float* W_qkv = (const float*)d_in[1];
    const float* b_qkv = (const float*)d_in[2];
    const float* W_out = (const float*)d_in[3];
    const float* b_out = (const float*)d_in[4];
    float* out = (float*)d_out;

    float* qkv;   cudaGetSymbolAddress((void**)&qkv,   g_qkv);
    float* attn;  cudaGetSymbolAddress((void**)&attn,  g_attn);
    float* xr;    cudaGetSymbolAddress((void**)&xr,    g_xr);
    float* wqkvr; cudaGetSymbolAddress((void**)&wqkvr, g_wqkvr);
    float* woutr; cudaGetSymbolAddress((void**)&woutr, g_woutr);

    cudaFuncSetAttribute(attn_tf32_kernel,
                         cudaFuncAttributeMaxDynamicSharedMemorySize, ATTN_SMEM);

    // 0) Pre-round inputs to tf32 (numerics-identical to load-time CVT)
    {
        int n4x = NTOK * D_MODEL / 4;
        int n4q = D_MODEL * 3 * D_MODEL / 4;
        int n4o = D_MODEL * D_MODEL / 4;
        round_tf32_kernel<<<(n4x + 255) / 256, 256>>>(x, xr, n4x);
        round_tf32_kernel<<<(n4q + 255) / 256, 256>>>(W_qkv, wqkvr, n4q);
        round_tf32_kernel<<<(n4o + 255) / 256, 256>>>(W_out, woutr, n4o);
    }

    // 1) QKV projection (epilogue rounds to tf32 for attention)
    dim3 g1(3 * D_MODEL / 128, NTOK / 128);
    gemm_tf32_kernel<true><<<g1, 256>>>(xr, wqkvr, b_qkv, qkv, NTOK, 3 * D_MODEL, D_MODEL);

    // 2) Causal flash attention
    dim3 g2(LSEQ / 64, NHEAD, NB);
    attn_tf32_kernel<<<g2, 128, ATTN_SMEM>>>();

    // 3) Output projection (plain fp32 epilogue)
    dim3 g3(D_MODEL / 128, NTOK / 128);
    gemm_tf32_kernel<false><<<g3, 256>>>(attn, woutr, b_out, out, NTOK, D_MODEL, D_MODEL);
}

// round 9
// speedup vs baseline: 1.6888x; 1.5215x over previous
#include <cuda_runtime.h>
#include <cuda_fp16.h>
#include <cstdint>

#define D_MODEL 1024
#define LSEQ    2048
#define NB      2
#define NHEAD   16
#define HD      64
#define NTOK    (NB * LSEQ)   // 4096

// Scratch (device globals — alloc-free per harness rules)
__device__ float  g_qkv[(size_t)NTOK * 3 * D_MODEL];      // [4096, 3072] (tf32-rounded fp32)
__device__ float  g_attn[(size_t)NTOK * D_MODEL];         // [4096, 1024] (tf32-rounded fp32)
__device__ __half g_xh[(size_t)NTOK * D_MODEL];           // x, fp16
__device__ __half g_wqkvh[(size_t)D_MODEL * 3 * D_MODEL]; // W_qkv, fp16
__device__ __half g_wouth[(size_t)D_MODEL * D_MODEL];     // W_out, fp16
__device__ __half g_attnh[(size_t)NTOK * D_MODEL];        // attn out, fp16 (for out-proj A)

// ---------------------------------------------------------------------------
// helpers
// ---------------------------------------------------------------------------
__device__ __forceinline__ uint32_t f2tf32(float f) {
    uint32_t r;
    asm("cvt.rna.tf32.f32 %0, %1;" : "=r"(r) : "f"(f));
    return r;
}

__device__ __forceinline__ void mma_tf32(float c[4], const uint32_t a[4], const uint32_t b[2]) {
    asm volatile(
        "mma.sync.aligned.m16n8k8.row.col.f32.tf32.tf32.f32 "
        "{%0,%1,%2,%3}, {%4,%5,%6,%7}, {%8,%9}, {%0,%1,%2,%3};"
        : "+f"(c[0]), "+f"(c[1]), "+f"(c[2]), "+f"(c[3])
        : "r"(a[0]), "r"(a[1]), "r"(a[2]), "r"(a[3]),
          "r"(b[0]), "r"(b[1]));
}

__device__ __forceinline__ void mma_f16(float c[4], const uint32_t a[4], const uint32_t b[2]) {
    asm volatile(
        "mma.sync.aligned.m16n8k16.row.col.f32.f16.f16.f32 "
        "{%0,%1,%2,%3}, {%4,%5,%6,%7}, {%8,%9}, {%0,%1,%2,%3};"
        : "+f"(c[0]), "+f"(c[1]), "+f"(c[2]), "+f"(c[3])
        : "r"(a[0]), "r"(a[1]), "r"(a[2]), "r"(a[3]),
          "r"(b[0]), "r"(b[1]));
}

__device__ __forceinline__ uint32_t smem_u32(const void* p) {
    return (uint32_t)__cvta_generic_to_shared(p);
}

__device__ __forceinline__ void ldmatrix_x4(uint32_t& r0, uint32_t& r1,
                                            uint32_t& r2, uint32_t& r3, uint32_t addr) {
    asm volatile("ldmatrix.sync.aligned.m8n8.x4.shared.b16 {%0,%1,%2,%3}, [%4];"
                 : "=r"(r0), "=r"(r1), "=r"(r2), "=r"(r3) : "r"(addr));
}
__device__ __forceinline__ void ldmatrix_x4_trans(uint32_t& r0, uint32_t& r1,
                                                  uint32_t& r2, uint32_t& r3, uint32_t addr) {
    asm volatile("ldmatrix.sync.aligned.m8n8.x4.trans.shared.b16 {%0,%1,%2,%3}, [%4];"
                 : "=r"(r0), "=r"(r1), "=r"(r2), "=r"(r3) : "r"(addr));
}

__device__ __forceinline__ void cp_async16(void* smem_dst, const void* gmem_src) {
    uint32_t dst = smem_u32(smem_dst);
    asm volatile("cp.async.cg.shared.global [%0], [%1], 16;" :: "r"(dst), "l"(gmem_src));
}
__device__ __forceinline__ void cp_async_commit() {
    asm volatile("cp.async.commit_group;");
}
template <int N>
__device__ __forceinline__ void cp_async_wait() {
    asm volatile("cp.async.wait_group %0;" :: "n"(N));
}

// ---------------------------------------------------------------------------
// Prep: fp32 -> fp16 (RN)
// ---------------------------------------------------------------------------
__global__ void to_f16_kernel(const float* __restrict__ src,
                              __half* __restrict__ dst, int n4) {
    int i = blockIdx.x * blockDim.x + threadIdx.x;
    if (i < n4) {
        float4 v = reinterpret_cast<const float4*>(src)[i];
        __half2 h0 = __floats2half2_rn(v.x, v.y);
        __half2 h1 = __floats2half2_rn(v.z, v.w);
        reinterpret_cast<__half2*>(dst)[2 * i]     = h0;
        reinterpret_cast<__half2*>(dst)[2 * i + 1] = h1;
    }
}

// ---------------------------------------------------------------------------
// fp16 tensor-core GEMM (m16n8k16), 3-stage cp.async, R4 ordering.
// Block 128x128, BK=32, 256 threads = 8 warps (2Mx4N), warp tile 64x32.
// A fragments via ldmatrix.x4 (As stride 40 halves -> 8-row txns distinct
// mod 128B); B via ldmatrix.x4.trans (Bs stride 136 halves, same property).
// ROUND_OUT: store tf32-rounded fp32 (for the tf32 attention consumer).
// ---------------------------------------------------------------------------
#define STAGES 3

template <bool ROUND_OUT>
__global__ __launch_bounds__(256, 2)
void gemm_f16_kernel(const __half* __restrict__ A,
                     const __half* __restrict__ B,
                     const float* __restrict__ bias,
                     float* __restrict__ C,
                     int M, int N, int K) {
    __shared__ __half As[STAGES][128][40];    // [m][k], pad to 40 halves
    __shared__ __half Bs[STAGES][32][136];    // [k][n], pad to 136 halves

    const int tid  = threadIdx.x;
    const int w    = tid >> 5;
    const int lane = tid & 31;
    const int gid  = lane >> 2;
    const int tig  = lane & 3;
    const int wm   = w >> 2;      // 0..1
    const int wn   = w & 3;       // 0..3

    const int rowBase = blockIdx.y * 128;
    const int colBase = blockIdx.x * 128;

    // cp.async: A tile 128x32 halves = 512 16B-chunks; B tile 32x128 = 512.
    const int a_r0 = tid >> 2,          a_c0 = (tid & 3) << 3;
    const int a_r1 = (tid + 256) >> 2,  a_c1 = ((tid + 256) & 3) << 3;
    const int b_r0 = tid >> 4,          b_c0 = (tid & 15) << 3;
    const int b_r1 = (tid + 256) >> 4,  b_c1 = ((tid + 256) & 15) << 3;

    // ldmatrix lane roles
    const int lrow = lane & 15;           // row within 16-row slab
    const int lhi  = (lane >> 4) << 3;    // +0 / +8 (k for A, n for B)

    float acc[4][4][4];
    #pragma unroll
    for (int mt = 0; mt < 4; mt++)
        #pragma unroll
        for (int nt = 0; nt < 4; nt++)
            #pragma unroll
            for (int r = 0; r < 4; r++) acc[mt][nt][r] = 0.0f;

    const int KITERS = K >> 5;   // BK=32

    #pragma unroll
    for (int s = 0; s < STAGES - 1; s++) {
        const int k0 = s << 5;
        cp_async16(&As[s][a_r0][a_c0], &A[(size_t)(rowBase + a_r0) * K + k0 + a_c0]);
        cp_async16(&As[s][a_r1][a_c1], &A[(size_t)(rowBase + a_r1) * K + k0 + a_c1]);
        cp_async16(&Bs[s][b_r0][b_c0], &B[(size_t)(k0 + b_r0) * N + colBase + b_c0]);
        cp_async16(&Bs[s][b_r1][b_c1], &B[(size_t)(k0 + b_r1) * N + colBase + b_c1]);
        cp_async_commit();
    }

    for (int iter = 0; iter < KITERS; iter++) {
        const int buf = iter % STAGES;
        cp_async_wait<STAGES - 2>();
        __syncthreads();

        #pragma unroll
        for (int kc = 0; kc < 2; kc++) {
            const int kb = kc << 4;
            uint32_t afr[4][4], bfr[4][2];
            #pragma unroll
            for (int mt = 0; mt < 4; mt++) {
                uint32_t addr = smem_u32(&As[buf][wm * 64 + mt * 16 + lrow][kb + lhi]);
                ldmatrix_x4(afr[mt][0], afr[mt][1], afr[mt][2], afr[mt][3], addr);
            }
            #pragma unroll
            for (int ntp = 0; ntp < 2; ntp++) {
                uint32_t addr = smem_u32(&Bs[buf][kb + lrow][wn * 32 + ntp * 16 + lhi]);
                uint32_t r0, r1, r2, r3;
                ldmatrix_x4_trans(r0, r1, r2, r3, addr);
                bfr[2 * ntp][0] = r0;  bfr[2 * ntp][1] = r1;
                bfr[2 * ntp + 1][0] = r2;  bfr[2 * ntp + 1][1] = r3;
            }
            #pragma unroll
            for (int mt = 0; mt < 4; mt++)
                #pragma unroll
                for (int nt = 0; nt < 4; nt++)
                    mma_f16(acc[mt][nt], afr[mt], bfr[nt]);
        }
        __syncthreads();

        const int kload = iter + STAGES - 1;
        if (kload < KITERS) {
            const int sbuf = kload % STAGES;
            const int k0 = kload << 5;
            cp_async16(&As[sbuf][a_r0][a_c0], &A[(size_t)(rowBase + a_r0) * K + k0 + a_c0]);
            cp_async16(&As[sbuf][a_r1][a_c1], &A[(size_t)(rowBase + a_r1) * K + k0 + a_c1]);
            cp_async16(&Bs[sbuf][b_r0][b_c0], &B[(size_t)(k0 + b_r0) * N + colBase + b_c0]);
            cp_async16(&Bs[sbuf][b_r1][b_c1], &B[(size_t)(k0 + b_r1) * N + colBase + b_c1]);
        }
        cp_async_commit();
    }

    #pragma unroll
    for (int mt = 0; mt < 4; mt++) {
        int r0 = rowBase + wm * 64 + mt * 16 + gid;
        #pragma unroll
        for (int nt = 0; nt < 4; nt++) {
            int c0 = colBase + wn * 32 + nt * 8 + 2 * tig;
            float bi0 = bias[c0], bi1 = bias[c0 + 1];
            float s00 = acc[mt][nt][0] + bi0, s01 = acc[mt][nt][1] + bi1;
            float s10 = acc[mt][nt][2] + bi0, s11 = acc[mt][nt][3] + bi1;
            float2 v0, v1;
            if (ROUND_OUT) {
                v0 = make_float2(__uint_as_float(f2tf32(s00)), __uint_as_float(f2tf32(s01)));
                v1 = make_float2(__uint_as_float(f2tf32(s10)), __uint_as_float(f2tf32(s11)));
            } else {
                v0 = make_float2(s00, s01);
                v1 = make_float2(s10, s11);
            }
            *reinterpret_cast<float2*>(&C[(size_t)r0       * N + c0]) = v0;
            *reinterpret_cast<float2*>(&C[(size_t)(r0 + 8) * N + c0]) = v1;
        }
    }
}

// ---------------------------------------------------------------------------
// tf32 TC flash attention (causal) — unchanged R7 (validated). Reads fp32
// tf32-rounded g_qkv; writes tf32-rounded g_attn AND fp16 g_attnh (out-proj A).
// ---------------------------------------------------------------------------
#define KS_F (64 * 68)
#define VS_F (64 * 72)
#define ATTN_SMEM ((2 * KS_F + 2 * VS_F) * 4)

__global__ __launch_bounds__(128, 3)
void attn_tf32_kernel() {
    extern __shared__ float sm[];
    float* KsB = sm;
    float* VsB = sm + 2 * KS_F;

    const int qt = gridDim.x - 1 - blockIdx.x;
    const int h  = blockIdx.y;
    const int b  = blockIdx.z;

    const int tid  = threadIdx.x;
    const int warp = tid >> 5;
    const int lane = tid & 31;
    const int gid  = lane >> 2;
    const int tig  = lane & 3;
    const int wrow = warp * 16;
    const int qrow0 = qt * 64;
    const float scale = 0.125f;

    uint32_t qf[8][4];
    {
        const float* Qb = g_qkv + (size_t)(b * LSEQ + qrow0 + wrow) * 3072 + h * 64;
        #pragma unroll
        for (int kc = 0; kc < 8; kc++) {
            qf[kc][0] = __float_as_uint(Qb[(size_t)gid       * 3072 + kc * 8 + tig    ]);
            qf[kc][1] = __float_as_uint(Qb[(size_t)(gid + 8) * 3072 + kc * 8 + tig    ]);
            qf[kc][2] = __float_as_uint(Qb[(size_t)gid       * 3072 + kc * 8 + tig + 4]);
            qf[kc][3] = __float_as_uint(Qb[(size_t)(gid + 8) * 3072 + kc * 8 + tig + 4]);
        }
    }

    float o[8][4];
    #pragma unroll
    for (int nt = 0; nt < 8; nt++)
        #pragma unroll
        for (int j = 0; j < 4; j++) o[nt][j] = 0.0f;
    float m0 = -1e30f, m8 = -1e30f, l0 = 0.0f, l8 = 0.0f;

    auto load_tile = [&](int kt, int buf) {
        const float* base = g_qkv + (size_t)(b * LSEQ + kt * 64) * 3072 + h * 64;
        float* kd = KsB + buf * KS_F;
        float* vd = VsB + buf * VS_F;
        #pragma unroll
        for (int c = tid; c < 1024; c += 128) {
            int r = c >> 4, c4 = (c & 15) << 2;
            const float* src = base + (size_t)r * 3072 + c4;
            cp_async16(kd + r * 68 + c4, src + 1024);
            cp_async16(vd + r * 72 + c4, src + 2048);
        }
    };

    load_tile(0, 0);
    cp_async_commit();

    for (int kt = 0; kt <= qt; kt++) {
        const int buf = kt & 1;
        cp_async_wait<0>();
        __syncthreads();

        if (kt < qt) load_tile(kt + 1, buf ^ 1);
        cp_async_commit();

        const float* Kb = KsB + buf * KS_F;
        const float* Vb = VsB + buf * VS_F;

        float s[8][4];
        #pragma unroll
        for (int nt = 0; nt < 8; nt++)
            #pragma unroll
            for (int j = 0; j < 4; j++) s[nt][j] = 0.0f;

        #pragma unroll
        for (int kc = 0; kc < 8; kc++) {
            #pragma unroll
            for (int nt = 0; nt < 8; nt++) {
                uint32_t bfr[2];
                bfr[0] = __float_as_uint(Kb[(nt * 8 + gid) * 68 + kc * 8 + tig    ]);
                bfr[1] = __float_as_uint(Kb[(nt * 8 + gid) * 68 + kc * 8 + tig + 4]);
                mma_tf32(s[nt], qf[kc], bfr);
            }
        }

        #pragma unroll
        for (int nt = 0; nt < 8; nt++)
            #pragma unroll
            for (int j = 0; j < 4; j++) s[nt][j] *= scale;

        if (kt == qt) {
            const int r0 = wrow + gid, r8 = r0 + 8;
            #pragma unroll
            for (int nt = 0; nt < 8; nt++) {
                int c = nt * 8 + 2 * tig;
                if (c     > r0) s[nt][0] = -1e30f;
                if (c + 1 > r0) s[nt][1] = -1e30f;
                if (c     > r8) s[nt][2] = -1e30f;
                if (c + 1 > r8) s[nt][3] = -1e30f;
            }
        }

        float mt0 = -1e30f, mt8 = -1e30f;
        #pragma unroll
        for (int nt = 0; nt < 8; nt++) {
            mt0 = fmaxf(mt0, fmaxf(s[nt][0], s[nt][1]));
            mt8 = fmaxf(mt8, fmaxf(s[nt][2], s[nt][3]));
        }
        #pragma unroll
        for (int off = 1; off < 4; off <<= 1) {
            mt0 = fmaxf(mt0, __shfl_xor_sync(0xffffffffu, mt0, off));
            mt8 = fmaxf(mt8, __shfl_xor_sync(0xffffffffu, mt8, off));
        }
        const float mn0 = fmaxf(m0, mt0), mn8 = fmaxf(m8, mt8);
        const float a0 = __expf(m0 - mn0), a8 = __expf(m8 - mn8);

        float rs0 = 0.0f, rs8 = 0.0f;
        #pragma unroll
        for (int nt = 0; nt < 8; nt++) {
            s[nt][0] = __expf(s[nt][0] - mn0);
            s[nt][1] = __expf(s[nt][1] - mn0);
            s[nt][2] = __expf(s[nt][2] - mn8);
            s[nt][3] = __expf(s[nt][3] - mn8);
            rs0 += s[nt][0] + s[nt][1];
            rs8 += s[nt][2] + s[nt][3];
            o[nt][0] *= a0; o[nt][1] *= a0;
            o[nt][2] *= a8; o[nt][3] *= a8;
        }
        #pragma unroll
        for (int off = 1; off < 4; off <<= 1) {
            rs0 += __shfl_xor_sync(0xffffffffu, rs0, off);
            rs8 += __shfl_xor_sync(0xffffffffu, rs8, off);
        }
        l0 = l0 * a0 + rs0;
        l8 = l8 * a8 + rs8;
        m0 = mn0; m8 = mn8;

        const int src0 = (lane & 0x1C) | (tig >> 1);
        const int src1 = src0 + 2;
        const bool odd = tig & 1;
        #pragma unroll
        for (int kc = 0; kc < 8; kc++) {
            float v00 = __shfl_sync(0xffffffffu, s[kc][0], src0);
            float v01 = __shfl_sync(0xffffffffu, s[kc][1], src0);
            float v20 = __shfl_sync(0xffffffffu, s[kc][2], src0);
            float v31 = __shfl_sync(0xffffffffu, s[kc][3], src0);
            float w00 = __shfl_sync(0xffffffffu, s[kc][0], src1);
            float w01 = __shfl_sync(0xffffffffu, s[kc][1], src1);
            float w20 = __shfl_sync(0xffffffffu, s[kc][2], src1);
            float w31 = __shfl_sync(0xffffffffu, s[kc][3], src1);
            uint32_t af[4];
            af[0] = f2tf32(odd ? v01 : v00);
            af[1] = f2tf32(odd ? v31 : v20);
            af[2] = f2tf32(odd ? w01 : w00);
            af[3] = f2tf32(odd ? w31 : w20);
            #pragma unroll
            for (int nt = 0; nt < 8; nt++) {
                uint32_t bfr[2];
                bfr[0] = __float_as_uint(Vb[(kc * 8 + tig    ) * 72 + nt * 8 + gid]);
                bfr[1] = __float_as_uint(Vb[(kc * 8 + tig + 4) * 72 + nt * 8 + gid]);
                mma_tf32(o[nt], af, bfr);
            }
        }
    }

    // Epilogue: store fp16 for the out-proj GEMM's A operand.
    const float inv0 = 1.0f / l0, inv8 = 1.0f / l8;
    __half* dsth = g_attnh + (size_t)(b * LSEQ + qrow0 + wrow) * D_MODEL + h * 64;
    #pragma unroll
    for (int nt = 0; nt < 8; nt++) {
        int c = nt * 8 + 2 * tig;
        __half2 h0 = __floats2half2_rn(o[nt][0] * inv0, o[nt][1] * inv0);
        __half2 h1 = __floats2half2_rn(o[nt][2] * inv8, o[nt][3] * inv8);
        *reinterpret_cast<__half2*>(dsth + (size_t)gid       * D_MODEL + c) = h0;
        *reinterpret_cast<__half2*>(dsth + (size_t)(gid + 8) * D_MODEL + c) = h1;
    }
}

// ---------------------------------------------------------------------------
extern "C" void kernel_launch(void* const* d_in, const int* in_sizes, int n_in,
                              void* d_out, int out_size) {
    const float* x     = (const float*)d_in[0];
    const float* W_qkv = (const float*)d_in[1];
    const float* b_qkv = (const float*)d_in[2];
    const float* W_out = (const float*)d_in[3];
    const float* b_out = (const float*)d_in[4];
    float* out = (float*)d_out;

    float*  qkv;   cudaGetSymbolAddress((void**)&qkv,   g_qkv);
    __half* xh;    cudaGetSymbolAddress((void**)&xh,    g_xh);
    __half* wqkvh; cudaGetSymbolAddress((void**)&wqkvh, g_wqkvh);
    __half* wouth; cudaGetSymbolAddress((void**)&wouth, g_wouth);
    __half* attnh; cudaGetSymbolAddress((void**)&attnh, g_attnh);

    cudaFuncSetAttribute(attn_tf32_kernel,
                         cudaFuncAttributeMaxDynamicSharedMemorySize, ATTN_SMEM);

    // 0) Convert inputs to fp16
    {
        int n4x = NTOK * D_MODEL / 4;
        int n4q = D_MODEL * 3 * D_MODEL / 4;
        int n4o = D_MODEL * D_MODEL / 4;
        to_f16_kernel<<<(n4x + 255) / 256, 256>>>(x, xh, n4x);
        to_f16_kernel<<<(n4q + 255) / 256, 256>>>(W_qkv, wqkvh, n4q);
        to_f16_kernel<<<(n4o + 255) / 256, 256>>>(W_out, wouth, n4o);
    }

    // 1) QKV projection (fp16 TC, epilogue rounds to tf32 for attention)
    dim3 g1(3 * D_MODEL / 128, NTOK / 128);
    gemm_f16_kernel<true><<<g1, 256>>>(xh, wqkvh, b_qkv, qkv, NTOK, 3 * D_MODEL, D_MODEL);

    // 2) Causal flash attention (tf32 TC) — writes fp16 g_attnh
    dim3 g2(LSEQ / 64, NHEAD, NB);
    attn_tf32_kernel<<<g2, 128, ATTN_SMEM>>>();

    // 3) Output projection (fp16 TC, fp32 epilogue)
    dim3 g3(D_MODEL / 128, NTOK / 128);
    gemm_f16_kernel<false><<<g3, 256>>>(attnh, wouth, b_out, out, NTOK, D_MODEL, D_MODEL);
}

// round 11
// speedup vs baseline: 2.2299x; 1.3204x over previous
#include <cuda_runtime.h>
#include <cuda_fp16.h>
#include <cstdint>

#define D_MODEL 1024
#define LSEQ    2048
#define NB      2
#define NHEAD   16
#define HD      64
#define NTOK    (NB * LSEQ)   // 4096

// Scratch (device globals — alloc-free per harness rules)
__device__ __half g_qkv[(size_t)NTOK * 3 * D_MODEL];      // [4096, 3072] fp16
__device__ __half g_xh[(size_t)NTOK * D_MODEL];           // x, fp16
__device__ __half g_wqkvh[(size_t)D_MODEL * 3 * D_MODEL]; // W_qkv, fp16
__device__ __half g_wouth[(size_t)D_MODEL * D_MODEL];     // W_out, fp16
__device__ __half g_attnh[(size_t)NTOK * D_MODEL];        // attn out, fp16

// ---------------------------------------------------------------------------
// helpers
// ---------------------------------------------------------------------------
__device__ __forceinline__ void mma_f16(float c[4], const uint32_t a[4], const uint32_t b[2]) {
    asm volatile(
        "mma.sync.aligned.m16n8k16.row.col.f32.f16.f16.f32 "
        "{%0,%1,%2,%3}, {%4,%5,%6,%7}, {%8,%9}, {%0,%1,%2,%3};"
        : "+f"(c[0]), "+f"(c[1]), "+f"(c[2]), "+f"(c[3])
        : "r"(a[0]), "r"(a[1]), "r"(a[2]), "r"(a[3]),
          "r"(b[0]), "r"(b[1]));
}

// Pack two fp32 into one fp16x2 register: lo -> bits[0:16), hi -> bits[16:32)
__device__ __forceinline__ uint32_t pack_half2(float lo, float hi) {
    uint32_t r;
    asm("cvt.rn.f16x2.f32 %0, %1, %2;" : "=r"(r) : "f"(hi), "f"(lo));
    return r;
}

__device__ __forceinline__ uint32_t smem_u32(const void* p) {
    return (uint32_t)__cvta_generic_to_shared(p);
}

__device__ __forceinline__ void ldmatrix_x4(uint32_t& r0, uint32_t& r1,
                                            uint32_t& r2, uint32_t& r3, uint32_t addr) {
    asm volatile("ldmatrix.sync.aligned.m8n8.x4.shared.b16 {%0,%1,%2,%3}, [%4];"
                 : "=r"(r0), "=r"(r1), "=r"(r2), "=r"(r3) : "r"(addr));
}
__device__ __forceinline__ void ldmatrix_x4_trans(uint32_t& r0, uint32_t& r1,
                                                  uint32_t& r2, uint32_t& r3, uint32_t addr) {
    asm volatile("ldmatrix.sync.aligned.m8n8.x4.trans.shared.b16 {%0,%1,%2,%3}, [%4];"
                 : "=r"(r0), "=r"(r1), "=r"(r2), "=r"(r3) : "r"(addr));
}

__device__ __forceinline__ void cp_async16(void* smem_dst, const void* gmem_src) {
    uint32_t dst = smem_u32(smem_dst);
    asm volatile("cp.async.cg.shared.global [%0], [%1], 16;" :: "r"(dst), "l"(gmem_src));
}
__device__ __forceinline__ void cp_async_commit() {
    asm volatile("cp.async.commit_group;");
}
template <int N>
__device__ __forceinline__ void cp_async_wait() {
    asm volatile("cp.async.wait_group %0;" :: "n"(N));
}

// ---------------------------------------------------------------------------
// Prep: fp32 -> fp16 (RN)
// ---------------------------------------------------------------------------
__global__ void to_f16_kernel(const float* __restrict__ src,
                              __half* __restrict__ dst, int n4) {
    int i = blockIdx.x * blockDim.x + threadIdx.x;
    if (i < n4) {
        float4 v = reinterpret_cast<const float4*>(src)[i];
        __half2 h0 = __floats2half2_rn(v.x, v.y);
        __half2 h1 = __floats2half2_rn(v.z, v.w);
        reinterpret_cast<__half2*>(dst)[2 * i]     = h0;
        reinterpret_cast<__half2*>(dst)[2 * i + 1] = h1;
    }
}

// ---------------------------------------------------------------------------
// fp16 tensor-core GEMM (m16n8k16), 3-stage cp.async, R4 ordering (proven).
// HALF_OUT: store fp16 (for g_qkv); else fp32 (final output).
// ---------------------------------------------------------------------------
#define STAGES 3

template <bool HALF_OUT>
__global__ __launch_bounds__(256, 2)
void gemm_f16_kernel(const __half* __restrict__ A,
                     const __half* __restrict__ B,
                     const float* __restrict__ bias,
                     void* __restrict__ Cv,
                     int M, int N, int K) {
    __shared__ __half As[STAGES][128][40];
    __shared__ __half Bs[STAGES][32][136];

    const int tid  = threadIdx.x;
    const int w    = tid >> 5;
    const int lane = tid & 31;
    const int gid  = lane >> 2;
    const int tig  = lane & 3;
    const int wm   = w >> 2;
    const int wn   = w & 3;

    const int rowBase = blockIdx.y * 128;
    const int colBase = blockIdx.x * 128;

    const int a_r0 = tid >> 2,          a_c0 = (tid & 3) << 3;
    const int a_r1 = (tid + 256) >> 2,  a_c1 = ((tid + 256) & 3) << 3;
    const int b_r0 = tid >> 4,          b_c0 = (tid & 15) << 3;
    const int b_r1 = (tid + 256) >> 4,  b_c1 = ((tid + 256) & 15) << 3;

    const int lrow = lane & 15;
    const int lhi  = (lane >> 4) << 3;

    float acc[4][4][4];
    #pragma unroll
    for (int mt = 0; mt < 4; mt++)
        #pragma unroll
        for (int nt = 0; nt < 4; nt++)
            #pragma unroll
            for (int r = 0; r < 4; r++) acc[mt][nt][r] = 0.0f;

    const int KITERS = K >> 5;

    #pragma unroll
    for (int s = 0; s < STAGES - 1; s++) {
        const int k0 = s << 5;
        cp_async16(&As[s][a_r0][a_c0], &A[(size_t)(rowBase + a_r0) * K + k0 + a_c0]);
        cp_async16(&As[s][a_r1][a_c1], &A[(size_t)(rowBase + a_r1) * K + k0 + a_c1]);
        cp_async16(&Bs[s][b_r0][b_c0], &B[(size_t)(k0 + b_r0) * N + colBase + b_c0]);
        cp_async16(&Bs[s][b_r1][b_c1], &B[(size_t)(k0 + b_r1) * N + colBase + b_c1]);
        cp_async_commit();
    }

    for (int iter = 0; iter < KITERS; iter++) {
        const int buf = iter % STAGES;
        cp_async_wait<STAGES - 2>();
        __syncthreads();

        #pragma unroll
        for (int kc = 0; kc < 2; kc++) {
            const int kb = kc << 4;
            uint32_t afr[4][4], bfr[4][2];
            #pragma unroll
            for (int mt = 0; mt < 4; mt++) {
                uint32_t addr = smem_u32(&As[buf][wm * 64 + mt * 16 + lrow][kb + lhi]);
                ldmatrix_x4(afr[mt][0], afr[mt][1], afr[mt][2], afr[mt][3], addr);
            }
            #pragma unroll
            for (int ntp = 0; ntp < 2; ntp++) {
                uint32_t addr = smem_u32(&Bs[buf][kb + lrow][wn * 32 + ntp * 16 + lhi]);
                uint32_t r0, r1, r2, r3;
                ldmatrix_x4_trans(r0, r1, r2, r3, addr);
                bfr[2 * ntp][0] = r0;      bfr[2 * ntp][1] = r1;
                bfr[2 * ntp + 1][0] = r2;  bfr[2 * ntp + 1][1] = r3;
            }
            #pragma unroll
            for (int mt = 0; mt < 4; mt++)
                #pragma unroll
                for (int nt = 0; nt < 4; nt++)
                    mma_f16(acc[mt][nt], afr[mt], bfr[nt]);
        }
        __syncthreads();

        const int kload = iter + STAGES - 1;
        if (kload < KITERS) {
            const int sbuf = kload % STAGES;
            const int k0 = kload << 5;
            cp_async16(&As[sbuf][a_r0][a_c0], &A[(size_t)(rowBase + a_r0) * K + k0 + a_c0]);
            cp_async16(&As[sbuf][a_r1][a_c1], &A[(size_t)(rowBase + a_r1) * K + k0 + a_c1]);
            cp_async16(&Bs[sbuf][b_r0][b_c0], &B[(size_t)(k0 + b_r0) * N + colBase + b_c0]);
            cp_async16(&Bs[sbuf][b_r1][b_c1], &B[(size_t)(k0 + b_r1) * N + colBase + b_c1]);
        }
        cp_async_commit();
    }

    #pragma unroll
    for (int mt = 0; mt < 4; mt++) {
        int r0 = rowBase + wm * 64 + mt * 16 + gid;
        #pragma unroll
        for (int nt = 0; nt < 4; nt++) {
            int c0 = colBase + wn * 32 + nt * 8 + 2 * tig;
            float bi0 = bias[c0], bi1 = bias[c0 + 1];
            float s00 = acc[mt][nt][0] + bi0, s01 = acc[mt][nt][1] + bi1;
            float s10 = acc[mt][nt][2] + bi0, s11 = acc[mt][nt][3] + bi1;
            if (HALF_OUT) {
                __half* Ch = (__half*)Cv;
                uint32_t p0 = pack_half2(s00, s01);
                uint32_t p1 = pack_half2(s10, s11);
                *reinterpret_cast<uint32_t*>(&Ch[(size_t)r0       * N + c0]) = p0;
                *reinterpret_cast<uint32_t*>(&Ch[(size_t)(r0 + 8) * N + c0]) = p1;
            } else {
                float* Cf = (float*)Cv;
                *reinterpret_cast<float2*>(&Cf[(size_t)r0       * N + c0]) = make_float2(s00, s01);
                *reinterpret_cast<float2*>(&Cf[(size_t)(r0 + 8) * N + c0]) = make_float2(s10, s11);
            }
        }
    }
}

// ---------------------------------------------------------------------------
// fp16 tensor-core flash attention (causal).
// 128 threads = 4 warps, warp = 16 Q rows, KV tiles of 64, double-buffered
// cp.async. Q/K/V fp16 in g_qkv. S C-fragment packs DIRECTLY into the P
// A-fragment (no shuffles). K frags: ldmatrix.x4 ([n][k] layout); V frags:
// ldmatrix.x4.trans ([k][n] layout). Stride 72 halves -> conflict-free.
// smem: 2 bufs x (K + V) x 64 x 72 halves = 36864 B.
// ---------------------------------------------------------------------------
#define KV_STRIDE 72
#define KV_TILE_H (64 * KV_STRIDE)
#define ATTN_SMEM (4 * KV_TILE_H * 2)   // bytes

__global__ __launch_bounds__(128, 3)
void attn_f16_kernel() {
    extern __shared__ __align__(16) __half smh[];
    __half* KsB = smh;                    // [2][64][72]
    __half* VsB = smh + 2 * KV_TILE_H;    // [2][64][72]

    const int qt = gridDim.x - 1 - blockIdx.x;   // heavy CTAs first
    const int h  = blockIdx.y;
    const int b  = blockIdx.z;

    const int tid  = threadIdx.x;
    const int warp = tid >> 5;
    const int lane = tid & 31;
    const int gid  = lane >> 2;
    const int tig  = lane & 3;
    const int lrow = lane & 15;
    const int lhi  = (lane >> 4) << 3;
    const int wrow = warp * 16;
    const int qrow0 = qt * 64;
    const float scale = 0.125f;

    // Q fragments (m16n8k16 A layout), direct 32-bit loads from gmem
    uint32_t qf[4][4];
    {
        const __half* Qb = g_qkv + (size_t)(b * LSEQ + qrow0 + wrow) * 3072 + h * 64;
        #pragma unroll
        for (int kc = 0; kc < 4; kc++) {
            qf[kc][0] = *reinterpret_cast<const uint32_t*>(&Qb[(size_t)gid       * 3072 + kc * 16 + 2 * tig    ]);
            qf[kc][1] = *reinterpret_cast<const uint32_t*>(&Qb[(size_t)(gid + 8) * 3072 + kc * 16 + 2 * tig    ]);
            qf[kc][2] = *reinterpret_cast<const uint32_t*>(&Qb[(size_t)gid       * 3072 + kc * 16 + 2 * tig + 8]);
            qf[kc][3] = *reinterpret_cast<const uint32_t*>(&Qb[(size_t)(gid + 8) * 3072 + kc * 16 + 2 * tig + 8]);
        }
    }

    float o[8][4];
    #pragma unroll
    for (int nt = 0; nt < 8; nt++)
        #pragma unroll
        for (int j = 0; j < 4; j++) o[nt][j] = 0.0f;
    float m0 = -1e30f, m8 = -1e30f, l0 = 0.0f, l8 = 0.0f;

    // Tile loader: 64x64 fp16 K and V = 512 16B-chunks each; 4+4 per thread
    auto load_tile = [&](int kt, int buf) {
        const __half* base = g_qkv + (size_t)(b * LSEQ + kt * 64) * 3072 + h * 64;
        __half* kd = KsB + buf * KV_TILE_H;
        __half* vd = VsB + buf * KV_TILE_H;
        #pragma unroll
        for (int c = tid; c < 512; c += 128) {
            int r = c >> 3, c8 = (c & 7) << 3;
            const __half* src = base + (size_t)r * 3072 + c8;
            cp_async16(kd + r * KV_STRIDE + c8, src + 1024);
            cp_async16(vd + r * KV_STRIDE + c8, src + 2048);
        }
    };

    load_tile(0, 0);
    cp_async_commit();

    for (int kt = 0; kt <= qt; kt++) {
        const int buf = kt & 1;
        cp_async_wait<0>();
        __syncthreads();

        if (kt < qt) load_tile(kt + 1, buf ^ 1);
        cp_async_commit();

        const __half* Kb = KsB + buf * KV_TILE_H;
        const __half* Vb = VsB + buf * KV_TILE_H;

        // S = Q @ K^T
        float s[8][4];
        #pragma unroll
        for (int nt = 0; nt < 8; nt++)
            #pragma unroll
            for (int j = 0; j < 4; j++) s[nt][j] = 0.0f;

        #pragma unroll
        for (int kc = 0; kc < 4; kc++) {
            #pragma unroll
            for (int ntp = 0; ntp < 4; ntp++) {
                // K stored [key(n)][d(k)] -> non-trans ldmatrix:
                // r0=(n0-7,k0-7) r1=(n8-15,k0-7) r2=(n0-7,k8-15) r3=(n8-15,k8-15)
                uint32_t addr = smem_u32(&Kb[(ntp * 16 + lrow) * KV_STRIDE + kc * 16 + lhi]);
                uint32_t r0, r1, r2, r3;
                ldmatrix_x4(r0, r1, r2, r3, addr);
                uint32_t b0[2] = {r0, r2};
                uint32_t b1[2] = {r1, r3};
                mma_f16(s[2 * ntp],     qf[kc], b0);
                mma_f16(s[2 * ntp + 1], qf[kc], b1);
            }
        }

        #pragma unroll
        for (int nt = 0; nt < 8; nt++)
            #pragma unroll
            for (int j = 0; j < 4; j++) s[nt][j] *= scale;

        if (kt == qt) {
            const int r0 = wrow + gid, r8 = r0 + 8;
            #pragma unroll
            for (int nt = 0; nt < 8; nt++) {
                int c = nt * 8 + 2 * tig;
                if (c     > r0) s[nt][0] = -1e30f;
                if (c + 1 > r0) s[nt][1] = -1e30f;
                if (c     > r8) s[nt][2] = -1e30f;
                if (c + 1 > r8) s[nt][3] = -1e30f;
            }
        }

        // Online softmax
        float mt0 = -1e30f, mt8 = -1e30f;
        #pragma unroll
        for (int nt = 0; nt < 8; nt++) {
            mt0 = fmaxf(mt0, fmaxf(s[nt][0], s[nt][1]));
            mt8 = fmaxf(mt8, fmaxf(s[nt][2], s[nt][3]));
        }
        #pragma unroll
        for (int off = 1; off < 4; off <<= 1) {
            mt0 = fmaxf(mt0, __shfl_xor_sync(0xffffffffu, mt0, off));
            mt8 = fmaxf(mt8, __shfl_xor_sync(0xffffffffu, mt8, off));
        }
        const float mn0 = fmaxf(m0, mt0), mn8 = fmaxf(m8, mt8);
        const float a0 = __expf(m0 - mn0), a8 = __expf(m8 - mn8);

        float rs0 = 0.0f, rs8 = 0.0f;
        #pragma unroll
        for (int nt = 0; nt < 8; nt++) {
            s[nt][0] = __expf(s[nt][0] - mn0);
            s[nt][1] = __expf(s[nt][1] - mn0);
            s[nt][2] = __expf(s[nt][2] - mn8);
            s[nt][3] = __expf(s[nt][3] - mn8);
            rs0 += s[nt][0] + s[nt][1];
            rs8 += s[nt][2] + s[nt][3];
            o[nt][0] *= a0; o[nt][1] *= a0;
            o[nt][2] *= a8; o[nt][3] *= a8;
        }
        #pragma unroll
        for (int off = 1; off < 4; off <<= 1) {
            rs0 += __shfl_xor_sync(0xffffffffu, rs0, off);
            rs8 += __shfl_xor_sync(0xffffffffu, rs8, off);
        }
        l0 = l0 * a0 + rs0;
        l8 = l8 * a8 + rs8;
        m0 = mn0; m8 = mn8;

        // O += P @ V : S C-fragment packs DIRECTLY into fp16 A-fragment.
        #pragma unroll
        for (int kc2 = 0; kc2 < 4; kc2++) {
            uint32_t af[4];
            af[0] = pack_half2(s[2 * kc2    ][0], s[2 * kc2    ][1]);
            af[1] = pack_half2(s[2 * kc2    ][2], s[2 * kc2    ][3]);
            af[2] = pack_half2(s[2 * kc2 + 1][0], s[2 * kc2 + 1][1]);
            af[3] = pack_half2(s[2 * kc2 + 1][2], s[2 * kc2 + 1][3]);
            #pragma unroll
            for (int ntp = 0; ntp < 4; ntp++) {
                // V stored [key(k)][d(n)] -> trans ldmatrix (same as GEMM B)
                uint32_t addr = smem_u32(&Vb[(kc2 * 16 + lrow) * KV_STRIDE + ntp * 16 + lhi]);
                uint32_t r0, r1, r2, r3;
                ldmatrix_x4_trans(r0, r1, r2, r3, addr);
                uint32_t b0[2] = {r0, r1};
                uint32_t b1[2] = {r2, r3};
                mma_f16(o[2 * ntp],     af, b0);
                mma_f16(o[2 * ntp + 1], af, b1);
            }
        }
    }

    // Epilogue: normalize, store fp16 for out-proj
    const float inv0 = 1.0f / l0, inv8 = 1.0f / l8;
    __half* dsth = g_attnh + (size_t)(b * LSEQ + qrow0 + wrow) * D_MODEL + h * 64;
    #pragma unroll
    for (int nt = 0; nt < 8; nt++) {
        int c = nt * 8 + 2 * tig;
        uint32_t h0 = pack_half2(o[nt][0] * inv0, o[nt][1] * inv0);
        uint32_t h1 = pack_half2(o[nt][2] * inv8, o[nt][3] * inv8);
        *reinterpret_cast<uint32_t*>(dsth + (size_t)gid       * D_MODEL + c) = h0;
        *reinterpret_cast<uint32_t*>(dsth + (size_t)(gid + 8) * D_MODEL + c) = h1;
    }
}

// ---------------------------------------------------------------------------
extern "C" void kernel_launch(void* const* d_in, const int* in_sizes, int n_in,
                              void* d_out, int out_size) {
    const float* x     = (const float*)d_in[0];
    const float* W_qkv = (const float*)d_in[1];
    const float* b_qkv = (const float*)d_in[2];
    const float* W_out = (const float*)d_in[3];
    const float* b_out = (const float*)d_in[4];
    float* out = (float*)d_out;

    __half* qkv;   cudaGetSymbolAddress((void**)&qkv,   g_qkv);
    __half* xh;    cudaGetSymbolAddress((void**)&xh,    g_xh);
    __half* wqkvh; cudaGetSymbolAddress((void**)&wqkvh, g_wqkvh);
    __half* wouth; cudaGetSymbolAddress((void**)&wouth, g_wouth);
    __half* attnh; cudaGetSymbolAddress((void**)&attnh, g_attnh);

    cudaFuncSetAttribute(attn_f16_kernel,
                         cudaFuncAttributeMaxDynamicSharedMemorySize, ATTN_SMEM);

    // 0) Convert inputs to fp16
    {
        int n4x = NTOK * D_MODEL / 4;
        int n4q = D_MODEL * 3 * D_MODEL / 4;
        int n4o = D_MODEL * D_MODEL / 4;
        to_f16_kernel<<<(n4x + 255) / 256, 256>>>(x, xh, n4x);
        to_f16_kernel<<<(n4q + 255) / 256, 256>>>(W_qkv, wqkvh, n4q);
        to_f16_kernel<<<(n4o + 255) / 256, 256>>>(W_out, wouth, n4o);
    }

    // 1) QKV projection (fp16 TC, fp16 output)
    dim3 g1(3 * D_MODEL / 128, NTOK / 128);
    gemm_f16_kernel<true><<<g1, 256>>>(xh, wqkvh, b_qkv, qkv, NTOK, 3 * D_MODEL, D_MODEL);

    // 2) Causal flash attention (fp16 TC)
    dim3 g2(LSEQ / 64, NHEAD, NB);
    attn_f16_kernel<<<g2, 128, ATTN_SMEM>>>();

    // 3) Output projection (fp16 TC, fp32 output)
    dim3 g3(D_MODEL / 128, NTOK / 128);
    gemm_f16_kernel<false><<<g3, 256>>>(attnh, wouth, b_out, out, NTOK, D_MODEL, D_MODEL);
}

// round 12
// speedup vs baseline: 2.3667x; 1.0613x over previous
#include <cuda_runtime.h>
#include <cuda_fp16.h>
#include <cstdint>

#define D_MODEL 1024
#define LSEQ    2048
#define NB      2
#define NHEAD   16
#define HD      64
#define NTOK    (NB * LSEQ)   // 4096

// Scratch (device globals — alloc-free per harness rules)
__device__ __half g_qkv[(size_t)NTOK * 3 * D_MODEL];      // [4096, 3072] fp16
__device__ __half g_xh[(size_t)NTOK * D_MODEL];           // x, fp16
__device__ __half g_wqkvh[(size_t)D_MODEL * 3 * D_MODEL]; // W_qkv, fp16
__device__ __half g_wouth[(size_t)D_MODEL * D_MODEL];     // W_out, fp16
__device__ __half g_attnh[(size_t)NTOK * D_MODEL];        // attn out, fp16

// ---------------------------------------------------------------------------
// helpers
// ---------------------------------------------------------------------------
__device__ __forceinline__ void mma_f16(float c[4], const uint32_t a[4], const uint32_t b[2]) {
    asm volatile(
        "mma.sync.aligned.m16n8k16.row.col.f32.f16.f16.f32 "
        "{%0,%1,%2,%3}, {%4,%5,%6,%7}, {%8,%9}, {%0,%1,%2,%3};"
        : "+f"(c[0]), "+f"(c[1]), "+f"(c[2]), "+f"(c[3])
        : "r"(a[0]), "r"(a[1]), "r"(a[2]), "r"(a[3]),
          "r"(b[0]), "r"(b[1]));
}

__device__ __forceinline__ uint32_t pack_half2(float lo, float hi) {
    uint32_t r;
    asm("cvt.rn.f16x2.f32 %0, %1, %2;" : "=r"(r) : "f"(hi), "f"(lo));
    return r;
}

__device__ __forceinline__ uint32_t smem_u32(const void* p) {
    return (uint32_t)__cvta_generic_to_shared(p);
}

__device__ __forceinline__ void ldmatrix_x4(uint32_t& r0, uint32_t& r1,
                                            uint32_t& r2, uint32_t& r3, uint32_t addr) {
    asm volatile("ldmatrix.sync.aligned.m8n8.x4.shared.b16 {%0,%1,%2,%3}, [%4];"
                 : "=r"(r0), "=r"(r1), "=r"(r2), "=r"(r3) : "r"(addr));
}
__device__ __forceinline__ void ldmatrix_x4_trans(uint32_t& r0, uint32_t& r1,
                                                  uint32_t& r2, uint32_t& r3, uint32_t addr) {
    asm volatile("ldmatrix.sync.aligned.m8n8.x4.trans.shared.b16 {%0,%1,%2,%3}, [%4];"
                 : "=r"(r0), "=r"(r1), "=r"(r2), "=r"(r3) : "r"(addr));
}

__device__ __forceinline__ void cp_async16(void* smem_dst, const void* gmem_src) {
    uint32_t dst = smem_u32(smem_dst);
    asm volatile("cp.async.cg.shared.global [%0], [%1], 16;" :: "r"(dst), "l"(gmem_src));
}
__device__ __forceinline__ void cp_async_commit() {
    asm volatile("cp.async.commit_group;");
}
template <int N>
__device__ __forceinline__ void cp_async_wait() {
    asm volatile("cp.async.wait_group %0;" :: "n"(N));
}

// ---------------------------------------------------------------------------
// Prep: fp32 -> fp16 (RN)
// ---------------------------------------------------------------------------
__global__ void to_f16_kernel(const float* __restrict__ src,
                              __half* __restrict__ dst, int n4) {
    int i = blockIdx.x * blockDim.x + threadIdx.x;
    if (i < n4) {
        float4 v = reinterpret_cast<const float4*>(src)[i];
        __half2 h0 = __floats2half2_rn(v.x, v.y);
        __half2 h1 = __floats2half2_rn(v.z, v.w);
        reinterpret_cast<__half2*>(dst)[2 * i]     = h0;
        reinterpret_cast<__half2*>(dst)[2 * i + 1] = h1;
    }
}

// ---------------------------------------------------------------------------
// fp16 tensor-core GEMM (m16n8k16), 4-stage cp.async, ONE sync per k-iter.
// Safety: refill at iter targets buffer (iter+3)%4, last read during iter-1's
// compute; the top-of-iter sync guarantees all warps finished iter-1 before
// any warp computes/refills at iter.
// Dynamic smem: 4*(128*40 + 32*136)*2 = 75776 B -> 2 CTAs/SM.
// HALF_OUT: store fp16 (g_qkv); else fp32 (final output).
// ---------------------------------------------------------------------------
#define STAGES 4
#define A_STG  (128 * 40)
#define B_STG  (32 * 136)
#define GEMM_SMEM ((STAGES * (A_STG + B_STG)) * 2)

template <bool HALF_OUT>
__global__ __launch_bounds__(256, 2)
void gemm_f16_kernel(const __half* __restrict__ A,
                     const __half* __restrict__ B,
                     const float* __restrict__ bias,
                     void* __restrict__ Cv,
                     int M, int N, int K) {
    extern __shared__ __align__(16) __half smh[];
    __half* As = smh;                    // [STAGES][128][40]
    __half* Bs = smh + STAGES * A_STG;   // [STAGES][32][136]

    const int tid  = threadIdx.x;
    const int w    = tid >> 5;
    const int lane = tid & 31;
    const int gid  = lane >> 2;
    const int tig  = lane & 3;
    const int wm   = w >> 2;
    const int wn   = w & 3;

    const int rowBase = blockIdx.y * 128;
    const int colBase = blockIdx.x * 128;

    const int a_r0 = tid >> 2,          a_c0 = (tid & 3) << 3;
    const int a_r1 = (tid + 256) >> 2,  a_c1 = ((tid + 256) & 3) << 3;
    const int b_r0 = tid >> 4,          b_c0 = (tid & 15) << 3;
    const int b_r1 = (tid + 256) >> 4,  b_c1 = ((tid + 256) & 15) << 3;

    const int lrow = lane & 15;
    const int lhi  = (lane >> 4) << 3;

    float acc[4][4][4];
    #pragma unroll
    for (int mt = 0; mt < 4; mt++)
        #pragma unroll
        for (int nt = 0; nt < 4; nt++)
            #pragma unroll
            for (int r = 0; r < 4; r++) acc[mt][nt][r] = 0.0f;

    const int KITERS = K >> 5;

    #pragma unroll
    for (int s = 0; s < STAGES - 1; s++) {
        const int k0 = s << 5;
        cp_async16(&As[s * A_STG + a_r0 * 40 + a_c0], &A[(size_t)(rowBase + a_r0) * K + k0 + a_c0]);
        cp_async16(&As[s * A_STG + a_r1 * 40 + a_c1], &A[(size_t)(rowBase + a_r1) * K + k0 + a_c1]);
        cp_async16(&Bs[s * B_STG + b_r0 * 136 + b_c0], &B[(size_t)(k0 + b_r0) * N + colBase + b_c0]);
        cp_async16(&Bs[s * B_STG + b_r1 * 136 + b_c1], &B[(size_t)(k0 + b_r1) * N + colBase + b_c1]);
        cp_async_commit();
    }

    for (int iter = 0; iter < KITERS; iter++) {
        const int buf = iter % STAGES;
        cp_async_wait<STAGES - 2>();
        __syncthreads();    // the ONLY barrier per iter

        const __half* Ab = As + buf * A_STG;
        const __half* Bb = Bs + buf * B_STG;

        #pragma unroll
        for (int kc = 0; kc < 2; kc++) {
            const int kb = kc << 4;
            uint32_t afr[4][4], bfr[4][2];
            #pragma unroll
            for (int mt = 0; mt < 4; mt++) {
                uint32_t addr = smem_u32(&Ab[(wm * 64 + mt * 16 + lrow) * 40 + kb + lhi]);
                ldmatrix_x4(afr[mt][0], afr[mt][1], afr[mt][2], afr[mt][3], addr);
            }
            #pragma unroll
            for (int ntp = 0; ntp < 2; ntp++) {
                uint32_t addr = smem_u32(&Bb[(kb + lrow) * 136 + wn * 32 + ntp * 16 + lhi]);
                uint32_t r0, r1, r2, r3;
                ldmatrix_x4_trans(r0, r1, r2, r3, addr);
                bfr[2 * ntp][0] = r0;      bfr[2 * ntp][1] = r1;
                bfr[2 * ntp + 1][0] = r2;  bfr[2 * ntp + 1][1] = r3;
            }
            #pragma unroll
            for (int mt = 0; mt < 4; mt++)
                #pragma unroll
                for (int nt = 0; nt < 4; nt++)
                    mma_f16(acc[mt][nt], afr[mt], bfr[nt]);
        }

        const int kload = iter + STAGES - 1;
        if (kload < KITERS) {
            const int sbuf = kload % STAGES;
            const int k0 = kload << 5;
            cp_async16(&As[sbuf * A_STG + a_r0 * 40 + a_c0], &A[(size_t)(rowBase + a_r0) * K + k0 + a_c0]);
            cp_async16(&As[sbuf * A_STG + a_r1 * 40 + a_c1], &A[(size_t)(rowBase + a_r1) * K + k0 + a_c1]);
            cp_async16(&Bs[sbuf * B_STG + b_r0 * 136 + b_c0], &B[(size_t)(k0 + b_r0) * N + colBase + b_c0]);
            cp_async16(&Bs[sbuf * B_STG + b_r1 * 136 + b_c1], &B[(size_t)(k0 + b_r1) * N + colBase + b_c1]);
        }
        cp_async_commit();
    }

    #pragma unroll
    for (int mt = 0; mt < 4; mt++) {
        int r0 = rowBase + wm * 64 + mt * 16 + gid;
        #pragma unroll
        for (int nt = 0; nt < 4; nt++) {
            int c0 = colBase + wn * 32 + nt * 8 + 2 * tig;
            float bi0 = bias[c0], bi1 = bias[c0 + 1];
            float s00 = acc[mt][nt][0] + bi0, s01 = acc[mt][nt][1] + bi1;
            float s10 = acc[mt][nt][2] + bi0, s11 = acc[mt][nt][3] + bi1;
            if (HALF_OUT) {
                __half* Ch = (__half*)Cv;
                *reinterpret_cast<uint32_t*>(&Ch[(size_t)r0       * N + c0]) = pack_half2(s00, s01);
                *reinterpret_cast<uint32_t*>(&Ch[(size_t)(r0 + 8) * N + c0]) = pack_half2(s10, s11);
            } else {
                float* Cf = (float*)Cv;
                *reinterpret_cast<float2*>(&Cf[(size_t)r0       * N + c0]) = make_float2(s00, s01);
                *reinterpret_cast<float2*>(&Cf[(size_t)(r0 + 8) * N + c0]) = make_float2(s10, s11);
            }
        }
    }
}

// ---------------------------------------------------------------------------
// fp16 tensor-core flash attention (causal) — unchanged R10 (234us total).
// ---------------------------------------------------------------------------
#define KV_STRIDE 72
#define KV_TILE_H (64 * KV_STRIDE)
#define ATTN_SMEM (4 * KV_TILE_H * 2)

__global__ __launch_bounds__(128, 3)
void attn_f16_kernel() {
    extern __shared__ __align__(16) __half smh[];
    __half* KsB = smh;
    __half* VsB = smh + 2 * KV_TILE_H;

    const int qt = gridDim.x - 1 - blockIdx.x;
    const int h  = blockIdx.y;
    const int b  = blockIdx.z;

    const int tid  = threadIdx.x;
    const int warp = tid >> 5;
    const int lane = tid & 31;
    const int gid  = lane >> 2;
    const int tig  = lane & 3;
    const int lrow = lane & 15;
    const int lhi  = (lane >> 4) << 3;
    const int wrow = warp * 16;
    const int qrow0 = qt * 64;
    const float scale = 0.125f;

    uint32_t qf[4][4];
    {
        const __half* Qb = g_qkv + (size_t)(b * LSEQ + qrow0 + wrow) * 3072 + h * 64;
        #pragma unroll
        for (int kc = 0; kc < 4; kc++) {
            qf[kc][0] = *reinterpret_cast<const uint32_t*>(&Qb[(size_t)gid       * 3072 + kc * 16 + 2 * tig    ]);
            qf[kc][1] = *reinterpret_cast<const uint32_t*>(&Qb[(size_t)(gid + 8) * 3072 + kc * 16 + 2 * tig    ]);
            qf[kc][2] = *reinterpret_cast<const uint32_t*>(&Qb[(size_t)gid       * 3072 + kc * 16 + 2 * tig + 8]);
            qf[kc][3] = *reinterpret_cast<const uint32_t*>(&Qb[(size_t)(gid + 8) * 3072 + kc * 16 + 2 * tig + 8]);
        }
    }

    float o[8][4];
    #pragma unroll
    for (int nt = 0; nt < 8; nt++)
        #pragma unroll
        for (int j = 0; j < 4; j++) o[nt][j] = 0.0f;
    float m0 = -1e30f, m8 = -1e30f, l0 = 0.0f, l8 = 0.0f;

    auto load_tile = [&](int kt, int buf) {
        const __half* base = g_qkv + (size_t)(b * LSEQ + kt * 64) * 3072 + h * 64;
        __half* kd = KsB + buf * KV_TILE_H;
        __half* vd = VsB + buf * KV_TILE_H;
        #pragma unroll
        for (int c = tid; c < 512; c += 128) {
            int r = c >> 3, c8 = (c & 7) << 3;
            const __half* src = base + (size_t)r * 3072 + c8;
            cp_async16(kd + r * KV_STRIDE + c8, src + 1024);
            cp_async16(vd + r * KV_STRIDE + c8, src + 2048);
        }
    };

    load_tile(0, 0);
    cp_async_commit();

    for (int kt = 0; kt <= qt; kt++) {
        const int buf = kt & 1;
        cp_async_wait<0>();
        __syncthreads();

        if (kt < qt) load_tile(kt + 1, buf ^ 1);
        cp_async_commit();

        const __half* Kb = KsB + buf * KV_TILE_H;
        const __half* Vb = VsB + buf * KV_TILE_H;

        float s[8][4];
        #pragma unroll
        for (int nt = 0; nt < 8; nt++)
            #pragma unroll
            for (int j = 0; j < 4; j++) s[nt][j] = 0.0f;

        #pragma unroll
        for (int kc = 0; kc < 4; kc++) {
            #pragma unroll
            for (int ntp = 0; ntp < 4; ntp++) {
                uint32_t addr = smem_u32(&Kb[(ntp * 16 + lrow) * KV_STRIDE + kc * 16 + lhi]);
                uint32_t r0, r1, r2, r3;
                ldmatrix_x4(r0, r1, r2, r3, addr);
                uint32_t b0[2] = {r0, r2};
                uint32_t b1[2] = {r1, r3};
                mma_f16(s[2 * ntp],     qf[kc], b0);
                mma_f16(s[2 * ntp + 1], qf[kc], b1);
            }
        }

        #pragma unroll
        for (int nt = 0; nt < 8; nt++)
            #pragma unroll
            for (int j = 0; j < 4; j++) s[nt][j] *= scale;

        if (kt == qt) {
            const int r0 = wrow + gid, r8 = r0 + 8;
            #pragma unroll
            for (int nt = 0; nt < 8; nt++) {
                int c = nt * 8 + 2 * tig;
                if (c     > r0) s[nt][0] = -1e30f;
                if (c + 1 > r0) s[nt][1] = -1e30f;
                if (c     > r8) s[nt][2] = -1e30f;
                if (c + 1 > r8) s[nt][3] = -1e30f;
            }
        }

        float mt0 = -1e30f, mt8 = -1e30f;
        #pragma unroll
        for (int nt = 0; nt < 8; nt++) {
            mt0 = fmaxf(mt0, fmaxf(s[nt][0], s[nt][1]));
            mt8 = fmaxf(mt8, fmaxf(s[nt][2], s[nt][3]));
        }
        #pragma unroll
        for (int off = 1; off < 4; off <<= 1) {
            mt0 = fmaxf(mt0, __shfl_xor_sync(0xffffffffu, mt0, off));
            mt8 = fmaxf(mt8, __shfl_xor_sync(0xffffffffu, mt8, off));
        }
        const float mn0 = fmaxf(m0, mt0), mn8 = fmaxf(m8, mt8);
        const float a0 = __expf(m0 - mn0), a8 = __expf(m8 - mn8);

        float rs0 = 0.0f, rs8 = 0.0f;
        #pragma unroll
        for (int nt = 0; nt < 8; nt++) {
            s[nt][0] = __expf(s[nt][0] - mn0);
            s[nt][1] = __expf(s[nt][1] - mn0);
            s[nt][2] = __expf(s[nt][2] - mn8);
            s[nt][3] = __expf(s[nt][3] - mn8);
            rs0 += s[nt][0] + s[nt][1];
            rs8 += s[nt][2] + s[nt][3];
            o[nt][0] *= a0; o[nt][1] *= a0;
            o[nt][2] *= a8; o[nt][3] *= a8;
        }
        #pragma unroll
        for (int off = 1; off < 4; off <<= 1) {
            rs0 += __shfl_xor_sync(0xffffffffu, rs0, off);
            rs8 += __shfl_xor_sync(0xffffffffu, rs8, off);
        }
        l0 = l0 * a0 + rs0;
        l8 = l8 * a8 + rs8;
        m0 = mn0; m8 = mn8;

        #pragma unroll
        for (int kc2 = 0; kc2 < 4; kc2++) {
            uint32_t af[4];
            af[0] = pack_half2(s[2 * kc2    ][0], s[2 * kc2    ][1]);
            af[1] = pack_half2(s[2 * kc2    ][2], s[2 * kc2    ][3]);
            af[2] = pack_half2(s[2 * kc2 + 1][0], s[2 * kc2 + 1][1]);
            af[3] = pack_half2(s[2 * kc2 + 1][2], s[2 * kc2 + 1][3]);
            #pragma unroll
            for (int ntp = 0; ntp < 4; ntp++) {
                uint32_t addr = smem_u32(&Vb[(kc2 * 16 + lrow) * KV_STRIDE + ntp * 16 + lhi]);
                uint32_t r0, r1, r2, r3;
                ldmatrix_x4_trans(r0, r1, r2, r3, addr);
                uint32_t b0[2] = {r0, r1};
                uint32_t b1[2] = {r2, r3};
                mma_f16(o[2 * ntp],     af, b0);
                mma_f16(o[2 * ntp + 1], af, b1);
            }
        }
    }

    const float inv0 = 1.0f / l0, inv8 = 1.0f / l8;
    __half* dsth = g_attnh + (size_t)(b * LSEQ + qrow0 + wrow) * D_MODEL + h * 64;
    #pragma unroll
    for (int nt = 0; nt < 8; nt++) {
        int c = nt * 8 + 2 * tig;
        *reinterpret_cast<uint32_t*>(dsth + (size_t)gid       * D_MODEL + c) =
            pack_half2(o[nt][0] * inv0, o[nt][1] * inv0);
        *reinterpret_cast<uint32_t*>(dsth + (size_t)(gid + 8) * D_MODEL + c) =
            pack_half2(o[nt][2] * inv8, o[nt][3] * inv8);
    }
}

// ---------------------------------------------------------------------------
extern "C" void kernel_launch(void* const* d_in, const int* in_sizes, int n_in,
                              void* d_out, int out_size) {
    const float* x     = (const float*)d_in[0];
    const float* W_qkv = (const float*)d_in[1];
    const float* b_qkv = (const float*)d_in[2];
    const float* W_out = (const float*)d_in[3];
    const float* b_out = (const float*)d_in[4];
    float* out = (float*)d_out;

    __half* qkv;   cudaGetSymbolAddress((void**)&qkv,   g_qkv);
    __half* xh;    cudaGetSymbolAddress((void**)&xh,    g_xh);
    __half* wqkvh; cudaGetSymbolAddress((void**)&wqkvh, g_wqkvh);
    __half* wouth; cudaGetSymbolAddress((void**)&wouth, g_wouth);
    __half* attnh; cudaGetSymbolAddress((void**)&attnh, g_attnh);

    cudaFuncSetAttribute(attn_f16_kernel,
                         cudaFuncAttributeMaxDynamicSharedMemorySize, ATTN_SMEM);
    cudaFuncSetAttribute(gemm_f16_kernel<true>,
                         cudaFuncAttributeMaxDynamicSharedMemorySize, GEMM_SMEM);
    cudaFuncSetAttribute(gemm_f16_kernel<false>,
                         cudaFuncAttributeMaxDynamicSharedMemorySize, GEMM_SMEM);

    // 0) Convert inputs to fp16
    {
        int n4x = NTOK * D_MODEL / 4;
        int n4q = D_MODEL * 3 * D_MODEL / 4;
        int n4o = D_MODEL * D_MODEL / 4;
        to_f16_kernel<<<(n4x + 255) / 256, 256>>>(x, xh, n4x);
        to_f16_kernel<<<(n4q + 255) / 256, 256>>>(W_qkv, wqkvh, n4q);
        to_f16_kernel<<<(n4o + 255) / 256, 256>>>(W_out, wouth, n4o);
    }

    // 1) QKV projection (fp16 TC, fp16 output)
    dim3 g1(3 * D_MODEL / 128, NTOK / 128);
    gemm_f16_kernel<true><<<g1, 256, GEMM_SMEM>>>(xh, wqkvh, b_qkv, qkv, NTOK, 3 * D_MODEL, D_MODEL);

    // 2) Causal flash attention (fp16 TC)
    dim3 g2(LSEQ / 64, NHEAD, NB);
    attn_f16_kernel<<<g2, 128, ATTN_SMEM>>>();

    // 3) Output projection (fp16 TC, fp32 output)
    dim3 g3(D_MODEL / 128, NTOK / 128);
    gemm_f16_kernel<false><<<g3, 256, GEMM_SMEM>>>(attnh, wouth, b_out, out, NTOK, D_MODEL, D_MODEL);
}